// round 13
// baseline (speedup 1.0000x reference)
#include <cuda_runtime.h>
#include <cuda_fp16.h>
#include <cstdint>

#define NN 50000
#define DIM_IN 256
#define HID 64
#define JC 960          // 15*HID concat width
#define MC 448          // mirror width: h(64)+c0raw(128)+c1raw(256)
#define OUTC 32
#define BN_EPS 1e-5f
#define E1MAX 800000
#define E2MAX 1600000
#define NBLK 196        // ceil(NN/256)

#define PACK_F32X2(out, lo, hi) \
    asm("mov.b64 %0, {%1, %2};" : "=l"(out) : "f"(lo), "f"(hi))
#define UNPACK_F32X2(lo, hi, in) \
    asm("mov.b64 {%0, %1}, %2;" : "=f"(lo), "=f"(hi) : "l"(in))
#define FMA_F32X2(d, a, b, c) \
    asm("fma.rn.f32x2 %0, %1, %2, %3;" : "=l"(d) : "l"(a), "l"(b), "l"(c))

// Persistent scratch: J = [h(64) | c0raw(128) | c1raw(256) | c2(512)] per row (fp32, exact).
__device__ float  d_J[(size_t)NN * JC];          // 192 MB
// fp16 mirror of gather sources only: [h | c0raw | c1raw]
__device__ __half d_M[(size_t)NN * MC];          // 44.8 MB
__device__ double d_stats[768];
__device__ unsigned d_bnctr[2];
__device__ float d_scale0[128], d_shift0[128];
__device__ float d_scale1[256], d_shift1[256];
__device__ float d_Wh2[JC * OUTC];
__device__ float d_bh2[OUTC];

// CSR-by-destination bins
__device__ int   d_deg1[NN], d_deg2[NN];
__device__ int   d_pos1[NN], d_pos2[NN];
__device__ int   d_ptr1[NN + 1], d_ptr2[NN + 1];
__device__ int   d_tmp1[NN], d_tmp2[NN];
__device__ int   d_bsum[2][256], d_boff[2][256];
__device__ __align__(16) int2 d_e1[E1MAX];
__device__ __align__(16) int2 d_e2[E2MAX];

// ---------------- zero / binning ----------------
__global__ void zero_small_kernel() {
    int i = blockIdx.x * blockDim.x + threadIdx.x;
    if (i < 768) d_stats[i] = 0.0;
    if (i < 2) d_bnctr[i] = 0u;
    if (i < NN) { d_deg1[i] = 0; d_deg2[i] = 0; d_pos1[i] = 0; d_pos2[i] = 0; }
}

__global__ void hist_kernel(const int* __restrict__ rows, int nE, int which) {
    int i = blockIdx.x * blockDim.x + threadIdx.x;
    if (i >= nE) return;
    int r = rows[i];
    atomicAdd(which ? &d_deg2[r] : &d_deg1[r], 1);
}

__global__ void scan_partial_kernel() {
    int g = blockIdx.x / NBLK;
    int blk = blockIdx.x - g * NBLK;
    const int* deg = g ? d_deg2 : d_deg1;
    int* tmp = g ? d_tmp2 : d_tmp1;

    int tid = threadIdx.x;
    int lane = tid & 31, w = tid >> 5;
    int i = blk * 256 + tid;
    int orig = (i < NN) ? deg[i] : 0;
    int v = orig;
#pragma unroll
    for (int o = 1; o < 32; o <<= 1) {
        int t = __shfl_up_sync(0xffffffffu, v, o);
        if (lane >= o) v += t;
    }
    __shared__ int wsum[8];
    if (lane == 31) wsum[w] = v;
    __syncthreads();
    if (w == 0) {
        int s = (lane < 8) ? wsum[lane] : 0;
#pragma unroll
        for (int o = 1; o < 8; o <<= 1) {
            int t = __shfl_up_sync(0xffffffffu, s, o);
            if (lane >= o) s += t;
        }
        if (lane < 8) wsum[lane] = s;
    }
    __syncthreads();
    int incl = v + (w > 0 ? wsum[w - 1] : 0);
    if (i < NN) tmp[i] = incl;
    if (tid == 255) d_bsum[g][blk] = incl;
}

__global__ void scan_tops_kernel() {
    __shared__ int sh[2][256];
    int g = threadIdx.x >> 8;
    int t = threadIdx.x & 255;
    int orig = (t < NBLK) ? d_bsum[g][t] : 0;
    sh[g][t] = orig;
    __syncthreads();
    for (int off = 1; off < 256; off <<= 1) {
        int add = (t >= off) ? sh[g][t - off] : 0;
        __syncthreads();
        sh[g][t] += add;
        __syncthreads();
    }
    d_boff[g][t] = sh[g][t] - orig;
}

__global__ void scan_add_kernel() {
    int g = blockIdx.x / NBLK;
    int blk = blockIdx.x - g * NBLK;
    int i = blk * 256 + threadIdx.x;
    if (i >= NN) return;
    const int* deg = g ? d_deg2 : d_deg1;
    const int* tmp = g ? d_tmp2 : d_tmp1;
    int* ptr = g ? d_ptr2 : d_ptr1;
    int off = d_boff[g][blk];
    int incl = tmp[i] + off;
    ptr[i] = incl - deg[i];
    if (i == NN - 1) ptr[NN] = incl;
}

__global__ void scatter_kernel(const int* __restrict__ rows,
                               const int* __restrict__ cols,
                               const float* __restrict__ vals,
                               int nE, int which) {
    int i = blockIdx.x * blockDim.x + threadIdx.x;
    if (i >= nE) return;
    int r = rows[i];
    int2 e = make_int2(cols[i], __float_as_int(vals[i]));
    if (which) {
        int p = d_ptr2[r] + atomicAdd(&d_pos2[r], 1);
        d_e2[p] = e;
    } else {
        int p = d_ptr1[r] + atomicAdd(&d_pos1[r], 1);
        d_e1[p] = e;
    }
}

// ---------------- embed: J[:,0:64] = relu(x @ W + b); mirror to d_M ----------------
__global__ void embed_kernel(const float* __restrict__ x,
                             const float* __restrict__ W,
                             const float* __restrict__ b) {
    __shared__ float Ws[64][64];
    __shared__ float xs[16][64];
    const int tx = threadIdx.x;
    const int ty = threadIdx.y;
    const int tid = ty * 64 + tx;
    const int row0 = blockIdx.x * 16;

    float acc[4] = {0.f, 0.f, 0.f, 0.f};
    for (int kt = 0; kt < 4; kt++) {
        for (int i = tid; i < 64 * 64; i += 256)
            Ws[i >> 6][i & 63] = W[(kt * 64 + (i >> 6)) * HID + (i & 63)];
        for (int i = tid; i < 16 * 64; i += 256)
            xs[i >> 6][i & 63] = x[(size_t)(row0 + (i >> 6)) * DIM_IN + kt * 64 + (i & 63)];
        __syncthreads();
#pragma unroll 16
        for (int kk = 0; kk < 64; kk++) {
            float wv = Ws[kk][tx];
#pragma unroll
            for (int r = 0; r < 4; r++) acc[r] += xs[ty * 4 + r][kk] * wv;
        }
        __syncthreads();
    }
    float bb = b[tx];
#pragma unroll
    for (int r = 0; r < 4; r++) {
        float v = acc[r] + bb;
        v = v > 0.f ? v : 0.f;
        int row = row0 + ty * 4 + r;
        d_J[(size_t)row * JC + tx] = v;
        d_M[(size_t)row * MC + tx] = __float2half_rn(v);
    }
}

// ---------------- fused SpMM gather: packed f32x2 accumulation ----------------
// C = floats per lane. Layout: C=2 -> lane*2; C=4 -> lane*4; C=8 -> lane*8 (contiguous).
template <int C>
__device__ __forceinline__ void accum_packed(unsigned long long* acc2,
                                             const __half* __restrict__ src,
                                             int lane, unsigned long long v2) {
    if constexpr (C == 2) {
        __half2 h = *reinterpret_cast<const __half2*>(src + lane * 2);
        float2 f = __half22float2(h);
        unsigned long long p;
        PACK_F32X2(p, f.x, f.y);
        FMA_F32X2(acc2[0], p, v2, acc2[0]);
    } else if constexpr (C == 4) {
        uint2 u = __ldg(reinterpret_cast<const uint2*>(src + lane * 4));
        float2 f0 = __half22float2(*reinterpret_cast<__half2*>(&u.x));
        float2 f1 = __half22float2(*reinterpret_cast<__half2*>(&u.y));
        unsigned long long p0, p1;
        PACK_F32X2(p0, f0.x, f0.y);
        PACK_F32X2(p1, f1.x, f1.y);
        FMA_F32X2(acc2[0], p0, v2, acc2[0]);
        FMA_F32X2(acc2[1], p1, v2, acc2[1]);
    } else {  // C == 8, contiguous lane*8
        uint4 q = __ldg(reinterpret_cast<const uint4*>(src + lane * 8));
        uint32_t wv[4] = {q.x, q.y, q.z, q.w};
#pragma unroll
        for (int i = 0; i < 4; i++) {
            float2 f = __half22float2(*reinterpret_cast<__half2*>(&wv[i]));
            unsigned long long p;
            PACK_F32X2(p, f.x, f.y);
            FMA_F32X2(acc2[i], p, v2, acc2[i]);
        }
    }
}

template <int C>
__device__ __forceinline__ float gather_one(const int2* __restrict__ edges,
                                            int s, int e, const __half* __restrict__ base,
                                            int lane, unsigned long long* acc2) {
#pragma unroll
    for (int i = 0; i < C / 2; i++) acc2[i] = 0ull;
    float sumv = 0.f;
    int j = s;
    if ((j & 1) && j < e) {
        int2 cv = __ldg(edges + j);
        float v = __int_as_float(cv.y);
        sumv += v;
        unsigned long long v2;
        PACK_F32X2(v2, v, v);
        accum_packed<C>(acc2, base + (size_t)cv.x * MC, lane, v2);
        j++;
    }
    for (; j + 8 <= e; j += 8) {
        int4 q[4];
        const int4* p = reinterpret_cast<const int4*>(edges + j);
#pragma unroll
        for (int u = 0; u < 4; u++) q[u] = __ldg(p + u);
#pragma unroll
        for (int u = 0; u < 4; u++) {
            float v0 = __int_as_float(q[u].y);
            float v1 = __int_as_float(q[u].w);
            unsigned long long v20, v21;
            PACK_F32X2(v20, v0, v0);
            PACK_F32X2(v21, v1, v1);
            sumv += v0;
            accum_packed<C>(acc2, base + (size_t)q[u].x * MC, lane, v20);
            sumv += v1;
            accum_packed<C>(acc2, base + (size_t)q[u].z * MC, lane, v21);
        }
    }
    for (; j < e; j++) {
        int2 cv = __ldg(edges + j);
        float v = __int_as_float(cv.y);
        sumv += v;
        unsigned long long v2;
        PACK_F32X2(v2, v, v);
        accum_packed<C>(acc2, base + (size_t)cv.x * MC, lane, v2);
    }
    return sumv;
}

// FOLD: 0 none, 1 bn0, 2 bn1. MIRROR: write fp16 copy.
// C=2/C=4 keep lane*C layout (mirrored, gathered downstream). C=8 uses lane*8 (head-only).
template <int C, int FOLD, int MIRROR>
__device__ __forceinline__ void store_acc(float* dst, __half* mdst, int lane,
                                          const unsigned long long* acc2, float sumv) {
    float o[C];
#pragma unroll
    for (int i = 0; i < C / 2; i++) UNPACK_F32X2(o[2 * i], o[2 * i + 1], acc2[i]);

    if constexpr (C == 2) {
        *reinterpret_cast<float2*>(dst + lane * 2) = make_float2(o[0], o[1]);
        if constexpr (MIRROR)
            *reinterpret_cast<__half2*>(mdst + lane * 2) = __floats2half2_rn(o[0], o[1]);
    } else if constexpr (C == 4) {
        if constexpr (FOLD) {
            const float* sc = (FOLD == 1) ? d_scale0 : d_scale1;
            const float* sh = (FOLD == 1) ? d_shift0 : d_shift1;
#pragma unroll
            for (int k = 0; k < 4; k++)
                o[k] = o[k] * sc[lane * 4 + k] + sumv * sh[lane * 4 + k];
        }
        *reinterpret_cast<float4*>(dst + lane * 4) = make_float4(o[0], o[1], o[2], o[3]);
        if constexpr (MIRROR) {
            __half2 h0 = __floats2half2_rn(o[0], o[1]);
            __half2 h1 = __floats2half2_rn(o[2], o[3]);
            uint2 u = make_uint2(*reinterpret_cast<uint32_t*>(&h0),
                                 *reinterpret_cast<uint32_t*>(&h1));
            *reinterpret_cast<uint2*>(mdst + lane * 4) = u;
        }
    } else {  // C == 8, lane*8 contiguous
        if constexpr (FOLD) {
            const float* sc = (FOLD == 1) ? d_scale0 : d_scale1;
            const float* sh = (FOLD == 1) ? d_shift0 : d_shift1;
#pragma unroll
            for (int k = 0; k < 8; k++)
                o[k] = o[k] * sc[lane * 8 + k] + sumv * sh[lane * 8 + k];
        }
        *reinterpret_cast<float4*>(dst + lane * 8) = make_float4(o[0], o[1], o[2], o[3]);
        *reinterpret_cast<float4*>(dst + lane * 8 + 4) = make_float4(o[4], o[5], o[6], o[7]);
    }
}

template <int C, int FOLD, int MIRROR>
__global__ void conv_kernel(int in_off, int out_off) {
    int row = (blockIdx.x * blockDim.x + threadIdx.x) >> 5;
    if (row >= NN) return;
    int lane = threadIdx.x & 31;
    const __half* base = d_M + in_off;
    float* dst = d_J + (size_t)row * JC + out_off;
    __half* mdst = d_M + (size_t)row * MC + out_off;
    unsigned long long acc2[C / 2];

    float sv = gather_one<C>(d_e1, __ldg(d_ptr1 + row), __ldg(d_ptr1 + row + 1), base, lane, acc2);
    store_acc<C, FOLD, MIRROR>(dst, mdst, lane, acc2, sv);

    sv = gather_one<C>(d_e2, __ldg(d_ptr2 + row), __ldg(d_ptr2 + row + 1), base, lane, acc2);
    store_acc<C, FOLD, MIRROR>(dst + 32 * C, mdst + 32 * C, lane, acc2, sv);
}

// ---------------- BatchNorm stats + fused finalize (last-block pattern) ----------------
__global__ void bn_stats_kernel(int off, int D, int statOff, int rowsPerBlock, int which,
                                const float* __restrict__ gamma,
                                const float* __restrict__ beta) {
    int f = threadIdx.x;
    int r0 = blockIdx.x * rowsPerBlock;
    int r1 = r0 + rowsPerBlock;
    if (r1 > NN) r1 = NN;
    float s = 0.f, q = 0.f;
    for (int r = r0; r < r1; r++) {
        float v = d_J[(size_t)r * JC + off + f];
        s += v;
        q += v * v;
    }
    atomicAdd(&d_stats[statOff + f], (double)s);
    atomicAdd(&d_stats[statOff + D + f], (double)q);

    __threadfence();
    __syncthreads();
    __shared__ bool isLast;
    if (f == 0) {
        unsigned t = atomicAdd(&d_bnctr[which], 1u);
        isLast = (t == gridDim.x - 1);
    }
    __syncthreads();
    if (isLast) {
        double sum, sq;
        asm volatile("ld.global.cg.f64 %0, [%1];" : "=d"(sum) : "l"(d_stats + statOff + f));
        asm volatile("ld.global.cg.f64 %0, [%1];" : "=d"(sq)  : "l"(d_stats + statOff + D + f));
        double m = sum / (double)NN;
        double var = sq / (double)NN - m * m;
        float sc = gamma[f] * rsqrtf((float)var + BN_EPS);
        float sh = beta[f] - (float)m * sc;
        if (which) { d_scale1[f] = sc; d_shift1[f] = sh; }
        else       { d_scale0[f] = sc; d_shift0[f] = sh; }
    }
}

// ---------------- head prescale: W' = sc*W, b' = b + sum sh*W ----------------
__global__ void head_prescale_kernel(const float* __restrict__ W,
                                     const float* __restrict__ b) {
    __shared__ float red[32][33];
    int t = threadIdx.x;
    int c = t & 31;
    int fg = t >> 5;   // 0..31
    float partial = 0.f;
    for (int f = fg; f < JC; f += 32) {
        float w = W[f * OUTC + c];
        float sc = 1.f, sh = 0.f;
        if (f >= 64 && f < 192) { sc = d_scale0[f - 64]; sh = d_shift0[f - 64]; }
        else if (f >= 192 && f < 448) { sc = d_scale1[f - 192]; sh = d_shift1[f - 192]; }
        d_Wh2[f * OUTC + c] = w * sc;
        partial += sh * w;
    }
    red[fg][c] = partial;
    __syncthreads();
    if (fg == 0) {
        float s = 0.f;
#pragma unroll
        for (int k = 0; k < 32; k++) s += red[k][c];
        d_bh2[c] = b[c] + s;
    }
}

// ---------------- head: out = J @ W' + b'  (f32x2 packed FMA) ----------------
#define KT 48
__global__ void head_kernel(float* __restrict__ out) {
    __shared__ float xs[KT][132];   // [kk][row], padded stride
    __shared__ float Ws[KT][32];
    const int tid = threadIdx.x;    // 256
    const int tx = tid & 7;         // col group: cols tx*4..tx*4+3
    const int ty = tid >> 3;        // row group: rows ty*4..ty*4+3 (0..31)
    const int row0 = blockIdx.x * 128;

    unsigned long long acc2[2][4];
#pragma unroll
    for (int p = 0; p < 2; p++)
#pragma unroll
        for (int j = 0; j < 4; j++) acc2[p][j] = 0ull;

    for (int kt = 0; kt < JC / KT; kt++) {
#pragma unroll
        for (int k = 0; k < 6; k++) {
            int idx4 = tid + k * 256;            // 0..1535
            int kk4 = idx4 % (KT / 4);
            int r = idx4 / (KT / 4);
            float4 v = make_float4(0.f, 0.f, 0.f, 0.f);
            int row = row0 + r;
            if (row < NN)
                v = *reinterpret_cast<const float4*>(d_J + (size_t)row * JC + kt * KT + kk4 * 4);
            xs[kk4 * 4 + 0][r] = v.x;
            xs[kk4 * 4 + 1][r] = v.y;
            xs[kk4 * 4 + 2][r] = v.z;
            xs[kk4 * 4 + 3][r] = v.w;
        }
#pragma unroll
        for (int k = 0; k < 6; k++) {
            int idx = tid + k * 256;             // 0..1535
            int fl = idx >> 5;
            int c = idx & 31;
            Ws[fl][c] = d_Wh2[(kt * KT + fl) * OUTC + c];
        }
        __syncthreads();
#pragma unroll 8
        for (int kk = 0; kk < KT; kk++) {
            unsigned long long xp0 = *reinterpret_cast<const unsigned long long*>(&xs[kk][ty * 4]);
            unsigned long long xp1 = *reinterpret_cast<const unsigned long long*>(&xs[kk][ty * 4 + 2]);
            float4 wv = *reinterpret_cast<const float4*>(&Ws[kk][tx * 4]);
            unsigned long long w0, w1, w2, w3;
            PACK_F32X2(w0, wv.x, wv.x);
            PACK_F32X2(w1, wv.y, wv.y);
            PACK_F32X2(w2, wv.z, wv.z);
            PACK_F32X2(w3, wv.w, wv.w);
            FMA_F32X2(acc2[0][0], xp0, w0, acc2[0][0]);
            FMA_F32X2(acc2[0][1], xp0, w1, acc2[0][1]);
            FMA_F32X2(acc2[0][2], xp0, w2, acc2[0][2]);
            FMA_F32X2(acc2[0][3], xp0, w3, acc2[0][3]);
            FMA_F32X2(acc2[1][0], xp1, w0, acc2[1][0]);
            FMA_F32X2(acc2[1][1], xp1, w1, acc2[1][1]);
            FMA_F32X2(acc2[1][2], xp1, w2, acc2[1][2]);
            FMA_F32X2(acc2[1][3], xp1, w3, acc2[1][3]);
        }
        __syncthreads();
    }

    float4 bb = *reinterpret_cast<const float4*>(d_bh2 + tx * 4);
    float bc[4] = {bb.x, bb.y, bb.z, bb.w};
    float accf[4][4];
#pragma unroll
    for (int p = 0; p < 2; p++)
#pragma unroll
        for (int j = 0; j < 4; j++) {
            float lo, hi;
            UNPACK_F32X2(lo, hi, acc2[p][j]);
            accf[2 * p][j] = lo;
            accf[2 * p + 1][j] = hi;
        }
#pragma unroll
    for (int i = 0; i < 4; i++) {
        int row = row0 + ty * 4 + i;
        if (row < NN) {
            float4 o = make_float4(accf[i][0] + bc[0], accf[i][1] + bc[1],
                                   accf[i][2] + bc[2], accf[i][3] + bc[3]);
            *reinterpret_cast<float4*>(out + (size_t)row * OUTC + tx * 4) = o;
        }
    }
}

extern "C" void kernel_launch(void* const* d_in, const int* in_sizes, int n_in,
                              void* d_out, int out_size) {
    const float* x   = (const float*)d_in[0];
    const int*   e1r = (const int*)d_in[1];
    const int*   e1c = (const int*)d_in[2];
    const float* e1v = (const float*)d_in[3];
    const int*   e2r = (const int*)d_in[4];
    const int*   e2c = (const int*)d_in[5];
    const float* e2v = (const float*)d_in[6];
    const float* We  = (const float*)d_in[7];
    const float* be  = (const float*)d_in[8];
    const float* g0  = (const float*)d_in[9];
    const float* b0  = (const float*)d_in[10];
    const float* g1  = (const float*)d_in[11];
    const float* b1  = (const float*)d_in[12];
    const float* Wh  = (const float*)d_in[13];
    const float* bh  = (const float*)d_in[14];
    float* out = (float*)d_out;

    const int E1 = in_sizes[1];
    const int E2 = in_sizes[4];

    static cudaStream_t s2 = nullptr;
    static cudaEvent_t evA = nullptr, evB = nullptr, evC = nullptr, evD = nullptr;
    if (!s2) {
        cudaStreamCreateWithFlags(&s2, cudaStreamNonBlocking);
        cudaEventCreateWithFlags(&evA, cudaEventDisableTiming);
        cudaEventCreateWithFlags(&evB, cudaEventDisableTiming);
        cudaEventCreateWithFlags(&evC, cudaEventDisableTiming);
        cudaEventCreateWithFlags(&evD, cudaEventDisableTiming);
    }

    // fork: binning on s2, embed on default stream
    cudaEventRecord(evA, 0);
    cudaStreamWaitEvent(s2, evA, 0);

    zero_small_kernel<<<(NN + 255) / 256, 256, 0, s2>>>();
    hist_kernel<<<(E1 + 255) / 256, 256, 0, s2>>>(e1r, E1, 0);
    hist_kernel<<<(E2 + 255) / 256, 256, 0, s2>>>(e2r, E2, 1);
    scan_partial_kernel<<<2 * NBLK, 256, 0, s2>>>();
    scan_tops_kernel<<<1, 512, 0, s2>>>();
    scan_add_kernel<<<2 * NBLK, 256, 0, s2>>>();
    scatter_kernel<<<(E1 + 255) / 256, 256, 0, s2>>>(e1r, e1c, e1v, E1, 0);
    scatter_kernel<<<(E2 + 255) / 256, 256, 0, s2>>>(e2r, e2c, e2v, E2, 1);

    embed_kernel<<<NN / 16, dim3(64, 4)>>>(x, We, be);

    cudaEventRecord(evB, s2);
    cudaStreamWaitEvent(0, evB, 0);

    const int gblocks = (NN + 7) / 8;  // 8 warps (rows) per 256-thread block

    // conv1: h16 -> c0 raw (fp32 J + fp16 mirror), cols [64,192)
    conv_kernel<2, 0, 1><<<gblocks, 256>>>(0, 64);

    // bn0 stats + fused finalize
    bn_stats_kernel<<<(NN + 127) / 128, 128>>>(64, 128, 0, 128, 0, g0, b0);

    // conv2: bn0(c0_16) -> c1 raw (fp32 J + fp16 mirror), cols [192,448)
    conv_kernel<4, 1, 1><<<gblocks, 256>>>(64, 192);

    // bn1 stats + fused finalize
    bn_stats_kernel<<<(NN + 127) / 128, 256>>>(192, 256, 256, 128, 1, g1, b1);

    // prescale overlapped with conv3 on s2 (depends only on BN scales)
    cudaEventRecord(evC, 0);
    cudaStreamWaitEvent(s2, evC, 0);
    head_prescale_kernel<<<1, 1024, 0, s2>>>(Wh, bh);
    cudaEventRecord(evD, s2);

    // conv3: bn1(c1_16) -> c2 (fp32 only), cols [448,960), lane*8 contiguous layout
    conv_kernel<8, 2, 0><<<gblocks, 256>>>(192, 448);

    // head GEMM after prescale + conv3
    cudaStreamWaitEvent(0, evD, 0);
    head_kernel<<<(NN + 127) / 128, 256>>>(out);
}

// round 14
// speedup vs baseline: 1.0912x; 1.0912x over previous
#include <cuda_runtime.h>
#include <cuda_fp16.h>
#include <cstdint>

#define NN 50000
#define DIM_IN 256
#define HID 64
#define JC 960          // 15*HID concat width
#define MC 448          // mirror width: h(64)+c0raw(128)+c1raw(256)
#define OUTC 32
#define BN_EPS 1e-5f
#define E1MAX 800000
#define E2MAX 1600000
#define NBLK 196        // ceil(NN/256)

#define PACK_F32X2(out, lo, hi) \
    asm("mov.b64 %0, {%1, %2};" : "=l"(out) : "f"(lo), "f"(hi))
#define UNPACK_F32X2(lo, hi, in) \
    asm("mov.b64 {%0, %1}, %2;" : "=f"(lo), "=f"(hi) : "l"(in))
#define FMA_F32X2(d, a, b, c) \
    asm("fma.rn.f32x2 %0, %1, %2, %3;" : "=l"(d) : "l"(a), "l"(b), "l"(c))

// Persistent scratch: J = [h(64) | c0raw(128) | c1raw(256) | c2(512)] per row (fp32, exact).
__device__ float  d_J[(size_t)NN * JC];          // 192 MB
// fp16 mirror of gather sources only: [h | c0raw | c1raw]
__device__ __half d_M[(size_t)NN * MC];          // 44.8 MB
__device__ double d_stats[768];
__device__ unsigned d_bnctr[2];
__device__ float d_scale0[128], d_shift0[128];
__device__ float d_scale1[256], d_shift1[256];
__device__ float d_Wh2[JC * OUTC];
__device__ float d_bh2[OUTC];

// CSR-by-destination bins
__device__ int   d_deg1[NN], d_deg2[NN];
__device__ int   d_pos1[NN], d_pos2[NN];
__device__ int   d_ptr1[NN + 1], d_ptr2[NN + 1];
__device__ int   d_tmp1[NN], d_tmp2[NN];
__device__ int   d_bsum[2][256], d_boff[2][256];
__device__ float d_sv1[NN], d_sv2[NN];           // per-row sum of edge vals (conv-invariant)
__device__ __align__(16) int2 d_e1[E1MAX];
__device__ __align__(16) int2 d_e2[E2MAX];

// ---------------- zero / binning ----------------
__global__ void zero_small_kernel() {
    int i = blockIdx.x * blockDim.x + threadIdx.x;
    if (i < 768) d_stats[i] = 0.0;
    if (i < 2) d_bnctr[i] = 0u;
    if (i < NN) {
        d_deg1[i] = 0; d_deg2[i] = 0; d_pos1[i] = 0; d_pos2[i] = 0;
        d_sv1[i] = 0.f; d_sv2[i] = 0.f;
    }
}

__global__ void hist_kernel(const int* __restrict__ rows,
                            const float* __restrict__ vals, int nE, int which) {
    int i = blockIdx.x * blockDim.x + threadIdx.x;
    if (i >= nE) return;
    int r = rows[i];
    float v = vals[i];
    if (which) {
        atomicAdd(&d_deg2[r], 1);
        atomicAdd(&d_sv2[r], v);
    } else {
        atomicAdd(&d_deg1[r], 1);
        atomicAdd(&d_sv1[r], v);
    }
}

__global__ void scan_partial_kernel() {
    int g = blockIdx.x / NBLK;
    int blk = blockIdx.x - g * NBLK;
    const int* deg = g ? d_deg2 : d_deg1;
    int* tmp = g ? d_tmp2 : d_tmp1;

    int tid = threadIdx.x;
    int lane = tid & 31, w = tid >> 5;
    int i = blk * 256 + tid;
    int orig = (i < NN) ? deg[i] : 0;
    int v = orig;
#pragma unroll
    for (int o = 1; o < 32; o <<= 1) {
        int t = __shfl_up_sync(0xffffffffu, v, o);
        if (lane >= o) v += t;
    }
    __shared__ int wsum[8];
    if (lane == 31) wsum[w] = v;
    __syncthreads();
    if (w == 0) {
        int s = (lane < 8) ? wsum[lane] : 0;
#pragma unroll
        for (int o = 1; o < 8; o <<= 1) {
            int t = __shfl_up_sync(0xffffffffu, s, o);
            if (lane >= o) s += t;
        }
        if (lane < 8) wsum[lane] = s;
    }
    __syncthreads();
    int incl = v + (w > 0 ? wsum[w - 1] : 0);
    if (i < NN) tmp[i] = incl;
    if (tid == 255) d_bsum[g][blk] = incl;
}

__global__ void scan_tops_kernel() {
    __shared__ int sh[2][256];
    int g = threadIdx.x >> 8;
    int t = threadIdx.x & 255;
    int orig = (t < NBLK) ? d_bsum[g][t] : 0;
    sh[g][t] = orig;
    __syncthreads();
    for (int off = 1; off < 256; off <<= 1) {
        int add = (t >= off) ? sh[g][t - off] : 0;
        __syncthreads();
        sh[g][t] += add;
        __syncthreads();
    }
    d_boff[g][t] = sh[g][t] - orig;
}

__global__ void scan_add_kernel() {
    int g = blockIdx.x / NBLK;
    int blk = blockIdx.x - g * NBLK;
    int i = blk * 256 + threadIdx.x;
    if (i >= NN) return;
    const int* deg = g ? d_deg2 : d_deg1;
    const int* tmp = g ? d_tmp2 : d_tmp1;
    int* ptr = g ? d_ptr2 : d_ptr1;
    int off = d_boff[g][blk];
    int incl = tmp[i] + off;
    ptr[i] = incl - deg[i];
    if (i == NN - 1) ptr[NN] = incl;
}

__global__ void scatter_kernel(const int* __restrict__ rows,
                               const int* __restrict__ cols,
                               const float* __restrict__ vals,
                               int nE, int which) {
    int i = blockIdx.x * blockDim.x + threadIdx.x;
    if (i >= nE) return;
    int r = rows[i];
    int2 e = make_int2(cols[i], __float_as_int(vals[i]));
    if (which) {
        int p = d_ptr2[r] + atomicAdd(&d_pos2[r], 1);
        d_e2[p] = e;
    } else {
        int p = d_ptr1[r] + atomicAdd(&d_pos1[r], 1);
        d_e1[p] = e;
    }
}

// ---------------- embed: J[:,0:64] = relu(x @ W + b); mirror to d_M ----------------
__global__ void embed_kernel(const float* __restrict__ x,
                             const float* __restrict__ W,
                             const float* __restrict__ b) {
    __shared__ float Ws[64][64];
    __shared__ float xs[16][64];
    const int tx = threadIdx.x;
    const int ty = threadIdx.y;
    const int tid = ty * 64 + tx;
    const int row0 = blockIdx.x * 16;

    float acc[4] = {0.f, 0.f, 0.f, 0.f};
    for (int kt = 0; kt < 4; kt++) {
        for (int i = tid; i < 64 * 64; i += 256)
            Ws[i >> 6][i & 63] = W[(kt * 64 + (i >> 6)) * HID + (i & 63)];
        for (int i = tid; i < 16 * 64; i += 256)
            xs[i >> 6][i & 63] = x[(size_t)(row0 + (i >> 6)) * DIM_IN + kt * 64 + (i & 63)];
        __syncthreads();
#pragma unroll 16
        for (int kk = 0; kk < 64; kk++) {
            float wv = Ws[kk][tx];
#pragma unroll
            for (int r = 0; r < 4; r++) acc[r] += xs[ty * 4 + r][kk] * wv;
        }
        __syncthreads();
    }
    float bb = b[tx];
#pragma unroll
    for (int r = 0; r < 4; r++) {
        float v = acc[r] + bb;
        v = v > 0.f ? v : 0.f;
        int row = row0 + ty * 4 + r;
        d_J[(size_t)row * JC + tx] = v;
        d_M[(size_t)row * MC + tx] = __float2half_rn(v);
    }
}

// ---------------- fused SpMM gather from fp16 mirror (+ BN fold) ----------------
template <int C>
__device__ __forceinline__ void accum_row16(float* acc, const __half* __restrict__ src,
                                            int lane, float v) {
    if constexpr (C == 2) {
        __half2 h = *reinterpret_cast<const __half2*>(src + lane * 2);
        float2 f = __half22float2(h);
        acc[0] += v * f.x; acc[1] += v * f.y;
    } else if constexpr (C == 4) {
        uint2 u = *reinterpret_cast<const uint2*>(src + lane * 4);
        float2 f0 = __half22float2(*reinterpret_cast<const __half2*>(&u.x));
        float2 f1 = __half22float2(*reinterpret_cast<const __half2*>(&u.y));
        acc[0] += v * f0.x; acc[1] += v * f0.y; acc[2] += v * f1.x; acc[3] += v * f1.y;
    } else {
        uint2 a = *reinterpret_cast<const uint2*>(src + lane * 4);
        uint2 bq = *reinterpret_cast<const uint2*>(src + 128 + lane * 4);
        float2 f0 = __half22float2(*reinterpret_cast<const __half2*>(&a.x));
        float2 f1 = __half22float2(*reinterpret_cast<const __half2*>(&a.y));
        float2 f2 = __half22float2(*reinterpret_cast<const __half2*>(&bq.x));
        float2 f3 = __half22float2(*reinterpret_cast<const __half2*>(&bq.y));
        acc[0] += v * f0.x; acc[1] += v * f0.y; acc[2] += v * f1.x; acc[3] += v * f1.y;
        acc[4] += v * f2.x; acc[5] += v * f2.y; acc[6] += v * f3.x; acc[7] += v * f3.y;
    }
}

template <int C>
__device__ __forceinline__ void gather_one(const int2* __restrict__ edges,
                                           int s, int e, const __half* __restrict__ base,
                                           int lane, float* acc) {
#pragma unroll
    for (int i = 0; i < C; i++) acc[i] = 0.f;
    int j = s;
    // scalar prologue to reach 16B alignment (edges is 16B-aligned, int2 = 8B)
    if ((j & 1) && j < e) {
        int2 cv = __ldg(edges + j);
        accum_row16<C>(acc, base + (size_t)cv.x * MC, lane, __int_as_float(cv.y));
        j++;
    }
    for (; j + 8 <= e; j += 8) {
        int4 q[4];
        const int4* p = reinterpret_cast<const int4*>(edges + j);
#pragma unroll
        for (int u = 0; u < 4; u++) q[u] = __ldg(p + u);
#pragma unroll
        for (int u = 0; u < 4; u++) {
            accum_row16<C>(acc, base + (size_t)q[u].x * MC, lane, __int_as_float(q[u].y));
            accum_row16<C>(acc, base + (size_t)q[u].z * MC, lane, __int_as_float(q[u].w));
        }
    }
    for (; j < e; j++) {
        int2 cv = __ldg(edges + j);
        accum_row16<C>(acc, base + (size_t)cv.x * MC, lane, __int_as_float(cv.y));
    }
}

// FOLD: 0 none, 1 bn0, 2 bn1 (applied to gathered input). MIRROR: write fp16 copy.
template <int C, int FOLD, int MIRROR>
__device__ __forceinline__ void store_acc(float* dst, __half* mdst, int lane,
                                          const float* acc, float sumv) {
    const float* sc = (FOLD == 1) ? d_scale0 : d_scale1;
    const float* sh = (FOLD == 1) ? d_shift0 : d_shift1;
    if constexpr (C == 2) {
        float2 o;
        if constexpr (FOLD) {
            o.x = acc[0] * sc[lane * 2] + sumv * sh[lane * 2];
            o.y = acc[1] * sc[lane * 2 + 1] + sumv * sh[lane * 2 + 1];
        } else { o.x = acc[0]; o.y = acc[1]; }
        *reinterpret_cast<float2*>(dst + lane * 2) = o;
        if constexpr (MIRROR)
            *reinterpret_cast<__half2*>(mdst + lane * 2) = __floats2half2_rn(o.x, o.y);
    } else if constexpr (C == 4) {
        float4 o;
        if constexpr (FOLD) {
            o.x = acc[0] * sc[lane * 4] + sumv * sh[lane * 4];
            o.y = acc[1] * sc[lane * 4 + 1] + sumv * sh[lane * 4 + 1];
            o.z = acc[2] * sc[lane * 4 + 2] + sumv * sh[lane * 4 + 2];
            o.w = acc[3] * sc[lane * 4 + 3] + sumv * sh[lane * 4 + 3];
        } else { o.x = acc[0]; o.y = acc[1]; o.z = acc[2]; o.w = acc[3]; }
        *reinterpret_cast<float4*>(dst + lane * 4) = o;
        if constexpr (MIRROR) {
            __half2 h0 = __floats2half2_rn(o.x, o.y);
            __half2 h1 = __floats2half2_rn(o.z, o.w);
            uint2 u = make_uint2(*reinterpret_cast<uint32_t*>(&h0),
                                 *reinterpret_cast<uint32_t*>(&h1));
            *reinterpret_cast<uint2*>(mdst + lane * 4) = u;
        }
    } else {
        float4 oa, ob;
        if constexpr (FOLD) {
            oa.x = acc[0] * sc[lane * 4] + sumv * sh[lane * 4];
            oa.y = acc[1] * sc[lane * 4 + 1] + sumv * sh[lane * 4 + 1];
            oa.z = acc[2] * sc[lane * 4 + 2] + sumv * sh[lane * 4 + 2];
            oa.w = acc[3] * sc[lane * 4 + 3] + sumv * sh[lane * 4 + 3];
            ob.x = acc[4] * sc[128 + lane * 4] + sumv * sh[128 + lane * 4];
            ob.y = acc[5] * sc[128 + lane * 4 + 1] + sumv * sh[128 + lane * 4 + 1];
            ob.z = acc[6] * sc[128 + lane * 4 + 2] + sumv * sh[128 + lane * 4 + 2];
            ob.w = acc[7] * sc[128 + lane * 4 + 3] + sumv * sh[128 + lane * 4 + 3];
        } else {
            oa.x = acc[0]; oa.y = acc[1]; oa.z = acc[2]; oa.w = acc[3];
            ob.x = acc[4]; ob.y = acc[5]; ob.z = acc[6]; ob.w = acc[7];
        }
        *reinterpret_cast<float4*>(dst + lane * 4) = oa;
        *reinterpret_cast<float4*>(dst + 128 + lane * 4) = ob;
    }
}

template <int C, int FOLD, int MIRROR>
__global__ void conv_kernel(int in_off, int out_off) {
    int row = (blockIdx.x * blockDim.x + threadIdx.x) >> 5;
    if (row >= NN) return;
    int lane = threadIdx.x & 31;
    const __half* base = d_M + in_off;
    float* dst = d_J + (size_t)row * JC + out_off;
    __half* mdst = d_M + (size_t)row * MC + out_off;
    float acc[C];

    float sv1 = FOLD ? __ldg(d_sv1 + row) : 0.f;
    float sv2 = FOLD ? __ldg(d_sv2 + row) : 0.f;

    gather_one<C>(d_e1, __ldg(d_ptr1 + row), __ldg(d_ptr1 + row + 1), base, lane, acc);
    store_acc<C, FOLD, MIRROR>(dst, mdst, lane, acc, sv1);

    gather_one<C>(d_e2, __ldg(d_ptr2 + row), __ldg(d_ptr2 + row + 1), base, lane, acc);
    store_acc<C, FOLD, MIRROR>(dst + 32 * C, mdst + 32 * C, lane, acc, sv2);
}

// ---------------- BatchNorm stats + fused finalize (last-block pattern) ----------------
__global__ void bn_stats_kernel(int off, int D, int statOff, int rowsPerBlock, int which,
                                const float* __restrict__ gamma,
                                const float* __restrict__ beta) {
    int f = threadIdx.x;
    int r0 = blockIdx.x * rowsPerBlock;
    int r1 = r0 + rowsPerBlock;
    if (r1 > NN) r1 = NN;
    float s = 0.f, q = 0.f;
    for (int r = r0; r < r1; r++) {
        float v = d_J[(size_t)r * JC + off + f];
        s += v;
        q += v * v;
    }
    atomicAdd(&d_stats[statOff + f], (double)s);
    atomicAdd(&d_stats[statOff + D + f], (double)q);

    __threadfence();
    __syncthreads();
    __shared__ bool isLast;
    if (f == 0) {
        unsigned t = atomicAdd(&d_bnctr[which], 1u);
        isLast = (t == gridDim.x - 1);
    }
    __syncthreads();
    if (isLast) {
        double sum, sq;
        asm volatile("ld.global.cg.f64 %0, [%1];" : "=d"(sum) : "l"(d_stats + statOff + f));
        asm volatile("ld.global.cg.f64 %0, [%1];" : "=d"(sq)  : "l"(d_stats + statOff + D + f));
        double m = sum / (double)NN;
        double var = sq / (double)NN - m * m;
        float sc = gamma[f] * rsqrtf((float)var + BN_EPS);
        float sh = beta[f] - (float)m * sc;
        if (which) { d_scale1[f] = sc; d_shift1[f] = sh; }
        else       { d_scale0[f] = sc; d_shift0[f] = sh; }
    }
}

// ---------------- head prescale: W' = sc*W, b' = b + sum sh*W ----------------
__global__ void head_prescale_kernel(const float* __restrict__ W,
                                     const float* __restrict__ b) {
    __shared__ float red[32][33];
    int t = threadIdx.x;
    int c = t & 31;
    int fg = t >> 5;   // 0..31
    float partial = 0.f;
    for (int f = fg; f < JC; f += 32) {
        float w = W[f * OUTC + c];
        float sc = 1.f, sh = 0.f;
        if (f >= 64 && f < 192) { sc = d_scale0[f - 64]; sh = d_shift0[f - 64]; }
        else if (f >= 192 && f < 448) { sc = d_scale1[f - 192]; sh = d_shift1[f - 192]; }
        d_Wh2[f * OUTC + c] = w * sc;
        partial += sh * w;
    }
    red[fg][c] = partial;
    __syncthreads();
    if (fg == 0) {
        float s = 0.f;
#pragma unroll
        for (int k = 0; k < 32; k++) s += red[k][c];
        d_bh2[c] = b[c] + s;
    }
}

// ---------------- head: out = J @ W' + b'  (f32x2 packed FMA) ----------------
#define KT 48
__global__ void head_kernel(float* __restrict__ out) {
    __shared__ float xs[KT][132];   // [kk][row], padded stride
    __shared__ float Ws[KT][32];
    const int tid = threadIdx.x;    // 256
    const int tx = tid & 7;         // col group: cols tx*4..tx*4+3
    const int ty = tid >> 3;        // row group: rows ty*4..ty*4+3 (0..31)
    const int row0 = blockIdx.x * 128;

    unsigned long long acc2[2][4];
#pragma unroll
    for (int p = 0; p < 2; p++)
#pragma unroll
        for (int j = 0; j < 4; j++) acc2[p][j] = 0ull;

    for (int kt = 0; kt < JC / KT; kt++) {
#pragma unroll
        for (int k = 0; k < 6; k++) {
            int idx4 = tid + k * 256;            // 0..1535
            int kk4 = idx4 % (KT / 4);
            int r = idx4 / (KT / 4);
            float4 v = make_float4(0.f, 0.f, 0.f, 0.f);
            int row = row0 + r;
            if (row < NN)
                v = *reinterpret_cast<const float4*>(d_J + (size_t)row * JC + kt * KT + kk4 * 4);
            xs[kk4 * 4 + 0][r] = v.x;
            xs[kk4 * 4 + 1][r] = v.y;
            xs[kk4 * 4 + 2][r] = v.z;
            xs[kk4 * 4 + 3][r] = v.w;
        }
#pragma unroll
        for (int k = 0; k < 6; k++) {
            int idx = tid + k * 256;             // 0..1535
            int fl = idx >> 5;
            int c = idx & 31;
            Ws[fl][c] = d_Wh2[(kt * KT + fl) * OUTC + c];
        }
        __syncthreads();
#pragma unroll 8
        for (int kk = 0; kk < KT; kk++) {
            unsigned long long xp0 = *reinterpret_cast<const unsigned long long*>(&xs[kk][ty * 4]);
            unsigned long long xp1 = *reinterpret_cast<const unsigned long long*>(&xs[kk][ty * 4 + 2]);
            float4 wv = *reinterpret_cast<const float4*>(&Ws[kk][tx * 4]);
            unsigned long long w0, w1, w2, w3;
            PACK_F32X2(w0, wv.x, wv.x);
            PACK_F32X2(w1, wv.y, wv.y);
            PACK_F32X2(w2, wv.z, wv.z);
            PACK_F32X2(w3, wv.w, wv.w);
            FMA_F32X2(acc2[0][0], xp0, w0, acc2[0][0]);
            FMA_F32X2(acc2[0][1], xp0, w1, acc2[0][1]);
            FMA_F32X2(acc2[0][2], xp0, w2, acc2[0][2]);
            FMA_F32X2(acc2[0][3], xp0, w3, acc2[0][3]);
            FMA_F32X2(acc2[1][0], xp1, w0, acc2[1][0]);
            FMA_F32X2(acc2[1][1], xp1, w1, acc2[1][1]);
            FMA_F32X2(acc2[1][2], xp1, w2, acc2[1][2]);
            FMA_F32X2(acc2[1][3], xp1, w3, acc2[1][3]);
        }
        __syncthreads();
    }

    float4 bb = *reinterpret_cast<const float4*>(d_bh2 + tx * 4);
    float bc[4] = {bb.x, bb.y, bb.z, bb.w};
    float accf[4][4];
#pragma unroll
    for (int p = 0; p < 2; p++)
#pragma unroll
        for (int j = 0; j < 4; j++) {
            float lo, hi;
            UNPACK_F32X2(lo, hi, acc2[p][j]);
            accf[2 * p][j] = lo;
            accf[2 * p + 1][j] = hi;
        }
#pragma unroll
    for (int i = 0; i < 4; i++) {
        int row = row0 + ty * 4 + i;
        if (row < NN) {
            float4 o = make_float4(accf[i][0] + bc[0], accf[i][1] + bc[1],
                                   accf[i][2] + bc[2], accf[i][3] + bc[3]);
            *reinterpret_cast<float4*>(out + (size_t)row * OUTC + tx * 4) = o;
        }
    }
}

extern "C" void kernel_launch(void* const* d_in, const int* in_sizes, int n_in,
                              void* d_out, int out_size) {
    const float* x   = (const float*)d_in[0];
    const int*   e1r = (const int*)d_in[1];
    const int*   e1c = (const int*)d_in[2];
    const float* e1v = (const float*)d_in[3];
    const int*   e2r = (const int*)d_in[4];
    const int*   e2c = (const int*)d_in[5];
    const float* e2v = (const float*)d_in[6];
    const float* We  = (const float*)d_in[7];
    const float* be  = (const float*)d_in[8];
    const float* g0  = (const float*)d_in[9];
    const float* b0  = (const float*)d_in[10];
    const float* g1  = (const float*)d_in[11];
    const float* b1  = (const float*)d_in[12];
    const float* Wh  = (const float*)d_in[13];
    const float* bh  = (const float*)d_in[14];
    float* out = (float*)d_out;

    const int E1 = in_sizes[1];
    const int E2 = in_sizes[4];

    static cudaStream_t s2 = nullptr;
    static cudaEvent_t evA = nullptr, evB = nullptr, evC = nullptr, evD = nullptr;
    if (!s2) {
        cudaStreamCreateWithFlags(&s2, cudaStreamNonBlocking);
        cudaEventCreateWithFlags(&evA, cudaEventDisableTiming);
        cudaEventCreateWithFlags(&evB, cudaEventDisableTiming);
        cudaEventCreateWithFlags(&evC, cudaEventDisableTiming);
        cudaEventCreateWithFlags(&evD, cudaEventDisableTiming);
    }

    // fork: binning on s2, embed on default stream
    cudaEventRecord(evA, 0);
    cudaStreamWaitEvent(s2, evA, 0);

    zero_small_kernel<<<(NN + 255) / 256, 256, 0, s2>>>();
    hist_kernel<<<(E1 + 255) / 256, 256, 0, s2>>>(e1r, e1v, E1, 0);
    hist_kernel<<<(E2 + 255) / 256, 256, 0, s2>>>(e2r, e2v, E2, 1);
    scan_partial_kernel<<<2 * NBLK, 256, 0, s2>>>();
    scan_tops_kernel<<<1, 512, 0, s2>>>();
    scan_add_kernel<<<2 * NBLK, 256, 0, s2>>>();
    scatter_kernel<<<(E1 + 255) / 256, 256, 0, s2>>>(e1r, e1c, e1v, E1, 0);
    scatter_kernel<<<(E2 + 255) / 256, 256, 0, s2>>>(e2r, e2c, e2v, E2, 1);

    embed_kernel<<<NN / 16, dim3(64, 4)>>>(x, We, be);

    cudaEventRecord(evB, s2);
    cudaStreamWaitEvent(0, evB, 0);

    const int gblocks = (NN + 7) / 8;  // 8 warps (rows) per 256-thread block

    // conv1: h16 -> c0 raw (fp32 J + fp16 mirror), cols [64,192)
    conv_kernel<2, 0, 1><<<gblocks, 256>>>(0, 64);

    // bn0 stats + fused finalize
    bn_stats_kernel<<<(NN + 127) / 128, 128>>>(64, 128, 0, 128, 0, g0, b0);

    // conv2: bn0(c0_16) -> c1 raw (fp32 J + fp16 mirror), cols [192,448)
    conv_kernel<4, 1, 1><<<gblocks, 256>>>(64, 192);

    // bn1 stats + fused finalize
    bn_stats_kernel<<<(NN + 127) / 128, 256>>>(192, 256, 256, 128, 1, g1, b1);

    // prescale overlapped with conv3 on s2 (depends only on BN scales)
    cudaEventRecord(evC, 0);
    cudaStreamWaitEvent(s2, evC, 0);
    head_prescale_kernel<<<1, 1024, 0, s2>>>(Wh, bh);
    cudaEventRecord(evD, s2);

    // conv3: bn1(c1_16) -> c2 (fp32 only), cols [448,960)
    conv_kernel<8, 2, 0><<<gblocks, 256>>>(192, 448);

    // head GEMM after prescale + conv3
    cudaStreamWaitEvent(0, evD, 0);
    head_kernel<<<(NN + 127) / 128, 256>>>(out);
}

// round 15
// speedup vs baseline: 1.1128x; 1.0198x over previous
#include <cuda_runtime.h>
#include <cuda_fp16.h>
#include <cstdint>

#define NN 50000
#define DIM_IN 256
#define HID 64
#define JC 960          // 15*HID concat width
#define MC 448          // mirror width: h(64)+c0raw(128)+c1raw(256)
#define OUTC 32
#define BN_EPS 1e-5f
#define E1MAX 800000
#define E2MAX 1600000
#define NBLK 196        // ceil(NN/256)

#define PACK_F32X2(out, lo, hi) \
    asm("mov.b64 %0, {%1, %2};" : "=l"(out) : "f"(lo), "f"(hi))
#define UNPACK_F32X2(lo, hi, in) \
    asm("mov.b64 {%0, %1}, %2;" : "=f"(lo), "=f"(hi) : "l"(in))
#define FMA_F32X2(d, a, b, c) \
    asm("fma.rn.f32x2 %0, %1, %2, %3;" : "=l"(d) : "l"(a), "l"(b), "l"(c))

// Persistent scratch: J = [h(64) | c0raw(128) | c1raw(256) | c2(512)] per row (fp32, exact).
__device__ float  d_J[(size_t)NN * JC];          // 192 MB
// fp16 mirror of gather sources only: [h | c0raw | c1raw]
__device__ __half d_M[(size_t)NN * MC];          // 44.8 MB
__device__ double d_stats[768];
__device__ unsigned d_bnctr[2];
__device__ float d_scale0[128], d_shift0[128];
__device__ float d_scale1[256], d_shift1[256];
__device__ float d_Wh2[JC * OUTC];
__device__ float d_bh2[OUTC];

// CSR-by-destination bins
__device__ int   d_deg1[NN], d_deg2[NN];
__device__ int   d_pos1[NN], d_pos2[NN];
__device__ int   d_ptr1[NN + 1], d_ptr2[NN + 1];
__device__ int   d_tmp1[NN], d_tmp2[NN];
__device__ int   d_bsum[2][256], d_boff[2][256];
__device__ __align__(16) int2 d_e1[E1MAX];
__device__ __align__(16) int2 d_e2[E2MAX];

// ---------------- zero / binning ----------------
__global__ void zero_small_kernel() {
    int i = blockIdx.x * blockDim.x + threadIdx.x;
    if (i < 768) d_stats[i] = 0.0;
    if (i < 2) d_bnctr[i] = 0u;
    if (i < NN) { d_deg1[i] = 0; d_deg2[i] = 0; d_pos1[i] = 0; d_pos2[i] = 0; }
}

__global__ void hist_kernel(const int* __restrict__ rows, int nE, int which) {
    int i = blockIdx.x * blockDim.x + threadIdx.x;
    if (i >= nE) return;
    int r = rows[i];
    atomicAdd(which ? &d_deg2[r] : &d_deg1[r], 1);
}

__global__ void scan_partial_kernel() {
    int g = blockIdx.x / NBLK;
    int blk = blockIdx.x - g * NBLK;
    const int* deg = g ? d_deg2 : d_deg1;
    int* tmp = g ? d_tmp2 : d_tmp1;

    int tid = threadIdx.x;
    int lane = tid & 31, w = tid >> 5;
    int i = blk * 256 + tid;
    int orig = (i < NN) ? deg[i] : 0;
    int v = orig;
#pragma unroll
    for (int o = 1; o < 32; o <<= 1) {
        int t = __shfl_up_sync(0xffffffffu, v, o);
        if (lane >= o) v += t;
    }
    __shared__ int wsum[8];
    if (lane == 31) wsum[w] = v;
    __syncthreads();
    if (w == 0) {
        int s = (lane < 8) ? wsum[lane] : 0;
#pragma unroll
        for (int o = 1; o < 8; o <<= 1) {
            int t = __shfl_up_sync(0xffffffffu, s, o);
            if (lane >= o) s += t;
        }
        if (lane < 8) wsum[lane] = s;
    }
    __syncthreads();
    int incl = v + (w > 0 ? wsum[w - 1] : 0);
    if (i < NN) tmp[i] = incl;
    if (tid == 255) d_bsum[g][blk] = incl;
}

__global__ void scan_tops_kernel() {
    __shared__ int sh[2][256];
    int g = threadIdx.x >> 8;
    int t = threadIdx.x & 255;
    int orig = (t < NBLK) ? d_bsum[g][t] : 0;
    sh[g][t] = orig;
    __syncthreads();
    for (int off = 1; off < 256; off <<= 1) {
        int add = (t >= off) ? sh[g][t - off] : 0;
        __syncthreads();
        sh[g][t] += add;
        __syncthreads();
    }
    d_boff[g][t] = sh[g][t] - orig;
}

__global__ void scan_add_kernel() {
    int g = blockIdx.x / NBLK;
    int blk = blockIdx.x - g * NBLK;
    int i = blk * 256 + threadIdx.x;
    if (i >= NN) return;
    const int* deg = g ? d_deg2 : d_deg1;
    const int* tmp = g ? d_tmp2 : d_tmp1;
    int* ptr = g ? d_ptr2 : d_ptr1;
    int off = d_boff[g][blk];
    int incl = tmp[i] + off;
    ptr[i] = incl - deg[i];
    if (i == NN - 1) ptr[NN] = incl;
}

__global__ void scatter_kernel(const int* __restrict__ rows,
                               const int* __restrict__ cols,
                               const float* __restrict__ vals,
                               int nE, int which) {
    int i = blockIdx.x * blockDim.x + threadIdx.x;
    if (i >= nE) return;
    int r = rows[i];
    int2 e = make_int2(cols[i], __float_as_int(vals[i]));
    if (which) {
        int p = d_ptr2[r] + atomicAdd(&d_pos2[r], 1);
        d_e2[p] = e;
    } else {
        int p = d_ptr1[r] + atomicAdd(&d_pos1[r], 1);
        d_e1[p] = e;
    }
}

// ---------------- embed: J[:,0:64] = relu(x @ W + b); mirror to d_M ----------------
__global__ void embed_kernel(const float* __restrict__ x,
                             const float* __restrict__ W,
                             const float* __restrict__ b) {
    __shared__ float Ws[64][64];
    __shared__ float xs[16][64];
    const int tx = threadIdx.x;
    const int ty = threadIdx.y;
    const int tid = ty * 64 + tx;
    const int row0 = blockIdx.x * 16;

    float acc[4] = {0.f, 0.f, 0.f, 0.f};
    for (int kt = 0; kt < 4; kt++) {
        for (int i = tid; i < 64 * 64; i += 256)
            Ws[i >> 6][i & 63] = W[(kt * 64 + (i >> 6)) * HID + (i & 63)];
        for (int i = tid; i < 16 * 64; i += 256)
            xs[i >> 6][i & 63] = x[(size_t)(row0 + (i >> 6)) * DIM_IN + kt * 64 + (i & 63)];
        __syncthreads();
#pragma unroll 16
        for (int kk = 0; kk < 64; kk++) {
            float wv = Ws[kk][tx];
#pragma unroll
            for (int r = 0; r < 4; r++) acc[r] += xs[ty * 4 + r][kk] * wv;
        }
        __syncthreads();
    }
    float bb = b[tx];
#pragma unroll
    for (int r = 0; r < 4; r++) {
        float v = acc[r] + bb;
        v = v > 0.f ? v : 0.f;
        int row = row0 + ty * 4 + r;
        d_J[(size_t)row * JC + tx] = v;
        d_M[(size_t)row * MC + tx] = __float2half_rn(v);
    }
}

// ---------------- fused SpMM gather from fp16 mirror (+ BN fold) ----------------
template <int C>
__device__ __forceinline__ void accum_row16(float* acc, const __half* __restrict__ src,
                                            int lane, float v) {
    if constexpr (C == 2) {
        __half2 h = *reinterpret_cast<const __half2*>(src + lane * 2);
        float2 f = __half22float2(h);
        acc[0] += v * f.x; acc[1] += v * f.y;
    } else if constexpr (C == 4) {
        uint2 u = *reinterpret_cast<const uint2*>(src + lane * 4);
        float2 f0 = __half22float2(*reinterpret_cast<const __half2*>(&u.x));
        float2 f1 = __half22float2(*reinterpret_cast<const __half2*>(&u.y));
        acc[0] += v * f0.x; acc[1] += v * f0.y; acc[2] += v * f1.x; acc[3] += v * f1.y;
    } else {
        uint2 a = *reinterpret_cast<const uint2*>(src + lane * 4);
        uint2 bq = *reinterpret_cast<const uint2*>(src + 128 + lane * 4);
        float2 f0 = __half22float2(*reinterpret_cast<const __half2*>(&a.x));
        float2 f1 = __half22float2(*reinterpret_cast<const __half2*>(&a.y));
        float2 f2 = __half22float2(*reinterpret_cast<const __half2*>(&bq.x));
        float2 f3 = __half22float2(*reinterpret_cast<const __half2*>(&bq.y));
        acc[0] += v * f0.x; acc[1] += v * f0.y; acc[2] += v * f1.x; acc[3] += v * f1.y;
        acc[4] += v * f2.x; acc[5] += v * f2.y; acc[6] += v * f3.x; acc[7] += v * f3.y;
    }
}

// NEED_SUM: accumulate sum of edge values (only needed when BN fold is applied downstream).
template <int C, int NEED_SUM>
__device__ __forceinline__ float gather_one(const int2* __restrict__ edges,
                                            int s, int e, const __half* __restrict__ base,
                                            int lane, float* acc) {
#pragma unroll
    for (int i = 0; i < C; i++) acc[i] = 0.f;
    float sumv = 0.f;
    int j = s;
    // scalar prologue to reach 16B alignment (edges is 16B-aligned, int2 = 8B)
    if ((j & 1) && j < e) {
        int2 cv = __ldg(edges + j);
        float v = __int_as_float(cv.y);
        if constexpr (NEED_SUM) sumv += v;
        accum_row16<C>(acc, base + (size_t)cv.x * MC, lane, v);
        j++;
    }
    for (; j + 8 <= e; j += 8) {
        int4 q[4];
        const int4* p = reinterpret_cast<const int4*>(edges + j);
#pragma unroll
        for (int u = 0; u < 4; u++) q[u] = __ldg(p + u);
#pragma unroll
        for (int u = 0; u < 4; u++) {
            float v0 = __int_as_float(q[u].y);
            float v1 = __int_as_float(q[u].w);
            if constexpr (NEED_SUM) sumv += v0;
            accum_row16<C>(acc, base + (size_t)q[u].x * MC, lane, v0);
            if constexpr (NEED_SUM) sumv += v1;
            accum_row16<C>(acc, base + (size_t)q[u].z * MC, lane, v1);
        }
    }
    for (; j < e; j++) {
        int2 cv = __ldg(edges + j);
        float v = __int_as_float(cv.y);
        if constexpr (NEED_SUM) sumv += v;
        accum_row16<C>(acc, base + (size_t)cv.x * MC, lane, v);
    }
    return sumv;
}

// FOLD: 0 none, 1 bn0, 2 bn1 (applied to gathered input). MIRROR: write fp16 copy.
template <int C, int FOLD, int MIRROR>
__device__ __forceinline__ void store_acc(float* dst, __half* mdst, int lane,
                                          const float* acc, float sumv) {
    const float* sc = (FOLD == 1) ? d_scale0 : d_scale1;
    const float* sh = (FOLD == 1) ? d_shift0 : d_shift1;
    if constexpr (C == 2) {
        float2 o;
        if constexpr (FOLD) {
            o.x = acc[0] * sc[lane * 2] + sumv * sh[lane * 2];
            o.y = acc[1] * sc[lane * 2 + 1] + sumv * sh[lane * 2 + 1];
        } else { o.x = acc[0]; o.y = acc[1]; }
        *reinterpret_cast<float2*>(dst + lane * 2) = o;
        if constexpr (MIRROR)
            *reinterpret_cast<__half2*>(mdst + lane * 2) = __floats2half2_rn(o.x, o.y);
    } else if constexpr (C == 4) {
        float4 o;
        if constexpr (FOLD) {
            o.x = acc[0] * sc[lane * 4] + sumv * sh[lane * 4];
            o.y = acc[1] * sc[lane * 4 + 1] + sumv * sh[lane * 4 + 1];
            o.z = acc[2] * sc[lane * 4 + 2] + sumv * sh[lane * 4 + 2];
            o.w = acc[3] * sc[lane * 4 + 3] + sumv * sh[lane * 4 + 3];
        } else { o.x = acc[0]; o.y = acc[1]; o.z = acc[2]; o.w = acc[3]; }
        *reinterpret_cast<float4*>(dst + lane * 4) = o;
        if constexpr (MIRROR) {
            __half2 h0 = __floats2half2_rn(o.x, o.y);
            __half2 h1 = __floats2half2_rn(o.z, o.w);
            uint2 u = make_uint2(*reinterpret_cast<uint32_t*>(&h0),
                                 *reinterpret_cast<uint32_t*>(&h1));
            *reinterpret_cast<uint2*>(mdst + lane * 4) = u;
        }
    } else {
        float4 oa, ob;
        if constexpr (FOLD) {
            oa.x = acc[0] * sc[lane * 4] + sumv * sh[lane * 4];
            oa.y = acc[1] * sc[lane * 4 + 1] + sumv * sh[lane * 4 + 1];
            oa.z = acc[2] * sc[lane * 4 + 2] + sumv * sh[lane * 4 + 2];
            oa.w = acc[3] * sc[lane * 4 + 3] + sumv * sh[lane * 4 + 3];
            ob.x = acc[4] * sc[128 + lane * 4] + sumv * sh[128 + lane * 4];
            ob.y = acc[5] * sc[128 + lane * 4 + 1] + sumv * sh[128 + lane * 4 + 1];
            ob.z = acc[6] * sc[128 + lane * 4 + 2] + sumv * sh[128 + lane * 4 + 2];
            ob.w = acc[7] * sc[128 + lane * 4 + 3] + sumv * sh[128 + lane * 4 + 3];
        } else {
            oa.x = acc[0]; oa.y = acc[1]; oa.z = acc[2]; oa.w = acc[3];
            ob.x = acc[4]; ob.y = acc[5]; ob.z = acc[6]; ob.w = acc[7];
        }
        *reinterpret_cast<float4*>(dst + lane * 4) = oa;
        *reinterpret_cast<float4*>(dst + 128 + lane * 4) = ob;
    }
}

template <int C, int FOLD, int MIRROR>
__global__ void conv_kernel(int in_off, int out_off) {
    int row = (blockIdx.x * blockDim.x + threadIdx.x) >> 5;
    if (row >= NN) return;
    int lane = threadIdx.x & 31;
    const __half* base = d_M + in_off;
    float* dst = d_J + (size_t)row * JC + out_off;
    __half* mdst = d_M + (size_t)row * MC + out_off;
    float acc[C];

    constexpr int NS = (FOLD != 0);
    float sv = gather_one<C, NS>(d_e1, __ldg(d_ptr1 + row), __ldg(d_ptr1 + row + 1), base, lane, acc);
    store_acc<C, FOLD, MIRROR>(dst, mdst, lane, acc, sv);

    sv = gather_one<C, NS>(d_e2, __ldg(d_ptr2 + row), __ldg(d_ptr2 + row + 1), base, lane, acc);
    store_acc<C, FOLD, MIRROR>(dst + 32 * C, mdst + 32 * C, lane, acc, sv);
}

// ---------------- BatchNorm stats + fused finalize (last-block pattern) ----------------
__global__ void bn_stats_kernel(int off, int D, int statOff, int rowsPerBlock, int which,
                                const float* __restrict__ gamma,
                                const float* __restrict__ beta) {
    int f = threadIdx.x;
    int r0 = blockIdx.x * rowsPerBlock;
    int r1 = r0 + rowsPerBlock;
    if (r1 > NN) r1 = NN;
    float s = 0.f, q = 0.f;
    for (int r = r0; r < r1; r++) {
        float v = d_J[(size_t)r * JC + off + f];
        s += v;
        q += v * v;
    }
    atomicAdd(&d_stats[statOff + f], (double)s);
    atomicAdd(&d_stats[statOff + D + f], (double)q);

    __threadfence();
    __syncthreads();
    __shared__ bool isLast;
    if (f == 0) {
        unsigned t = atomicAdd(&d_bnctr[which], 1u);
        isLast = (t == gridDim.x - 1);
    }
    __syncthreads();
    if (isLast) {
        double sum, sq;
        asm volatile("ld.global.cg.f64 %0, [%1];" : "=d"(sum) : "l"(d_stats + statOff + f));
        asm volatile("ld.global.cg.f64 %0, [%1];" : "=d"(sq)  : "l"(d_stats + statOff + D + f));
        double m = sum / (double)NN;
        double var = sq / (double)NN - m * m;
        float sc = gamma[f] * rsqrtf((float)var + BN_EPS);
        float sh = beta[f] - (float)m * sc;
        if (which) { d_scale1[f] = sc; d_shift1[f] = sh; }
        else       { d_scale0[f] = sc; d_shift0[f] = sh; }
    }
}

// ---------------- head prescale: W' = sc*W, b' = b + sum sh*W ----------------
__global__ void head_prescale_kernel(const float* __restrict__ W,
                                     const float* __restrict__ b) {
    __shared__ float red[32][33];
    int t = threadIdx.x;
    int c = t & 31;
    int fg = t >> 5;   // 0..31
    float partial = 0.f;
    for (int f = fg; f < JC; f += 32) {
        float w = W[f * OUTC + c];
        float sc = 1.f, sh = 0.f;
        if (f >= 64 && f < 192) { sc = d_scale0[f - 64]; sh = d_shift0[f - 64]; }
        else if (f >= 192 && f < 448) { sc = d_scale1[f - 192]; sh = d_shift1[f - 192]; }
        d_Wh2[f * OUTC + c] = w * sc;
        partial += sh * w;
    }
    red[fg][c] = partial;
    __syncthreads();
    if (fg == 0) {
        float s = 0.f;
#pragma unroll
        for (int k = 0; k < 32; k++) s += red[k][c];
        d_bh2[c] = b[c] + s;
    }
}

// ---------------- head: out = J @ W' + b'  (f32x2 packed FMA) ----------------
#define KT 48
__global__ void head_kernel(float* __restrict__ out) {
    __shared__ float xs[KT][132];   // [kk][row], padded stride
    __shared__ float Ws[KT][32];
    const int tid = threadIdx.x;    // 256
    const int tx = tid & 7;         // col group: cols tx*4..tx*4+3
    const int ty = tid >> 3;        // row group: rows ty*4..ty*4+3 (0..31)
    const int row0 = blockIdx.x * 128;

    unsigned long long acc2[2][4];
#pragma unroll
    for (int p = 0; p < 2; p++)
#pragma unroll
        for (int j = 0; j < 4; j++) acc2[p][j] = 0ull;

    for (int kt = 0; kt < JC / KT; kt++) {
#pragma unroll
        for (int k = 0; k < 6; k++) {
            int idx4 = tid + k * 256;            // 0..1535
            int kk4 = idx4 % (KT / 4);
            int r = idx4 / (KT / 4);
            float4 v = make_float4(0.f, 0.f, 0.f, 0.f);
            int row = row0 + r;
            if (row < NN)
                v = *reinterpret_cast<const float4*>(d_J + (size_t)row * JC + kt * KT + kk4 * 4);
            xs[kk4 * 4 + 0][r] = v.x;
            xs[kk4 * 4 + 1][r] = v.y;
            xs[kk4 * 4 + 2][r] = v.z;
            xs[kk4 * 4 + 3][r] = v.w;
        }
#pragma unroll
        for (int k = 0; k < 6; k++) {
            int idx = tid + k * 256;             // 0..1535
            int fl = idx >> 5;
            int c = idx & 31;
            Ws[fl][c] = d_Wh2[(kt * KT + fl) * OUTC + c];
        }
        __syncthreads();
#pragma unroll 8
        for (int kk = 0; kk < KT; kk++) {
            unsigned long long xp0 = *reinterpret_cast<const unsigned long long*>(&xs[kk][ty * 4]);
            unsigned long long xp1 = *reinterpret_cast<const unsigned long long*>(&xs[kk][ty * 4 + 2]);
            float4 wv = *reinterpret_cast<const float4*>(&Ws[kk][tx * 4]);
            unsigned long long w0, w1, w2, w3;
            PACK_F32X2(w0, wv.x, wv.x);
            PACK_F32X2(w1, wv.y, wv.y);
            PACK_F32X2(w2, wv.z, wv.z);
            PACK_F32X2(w3, wv.w, wv.w);
            FMA_F32X2(acc2[0][0], xp0, w0, acc2[0][0]);
            FMA_F32X2(acc2[0][1], xp0, w1, acc2[0][1]);
            FMA_F32X2(acc2[0][2], xp0, w2, acc2[0][2]);
            FMA_F32X2(acc2[0][3], xp0, w3, acc2[0][3]);
            FMA_F32X2(acc2[1][0], xp1, w0, acc2[1][0]);
            FMA_F32X2(acc2[1][1], xp1, w1, acc2[1][1]);
            FMA_F32X2(acc2[1][2], xp1, w2, acc2[1][2]);
            FMA_F32X2(acc2[1][3], xp1, w3, acc2[1][3]);
        }
        __syncthreads();
    }

    float4 bb = *reinterpret_cast<const float4*>(d_bh2 + tx * 4);
    float bc[4] = {bb.x, bb.y, bb.z, bb.w};
    float accf[4][4];
#pragma unroll
    for (int p = 0; p < 2; p++)
#pragma unroll
        for (int j = 0; j < 4; j++) {
            float lo, hi;
            UNPACK_F32X2(lo, hi, acc2[p][j]);
            accf[2 * p][j] = lo;
            accf[2 * p + 1][j] = hi;
        }
#pragma unroll
    for (int i = 0; i < 4; i++) {
        int row = row0 + ty * 4 + i;
        if (row < NN) {
            float4 o = make_float4(accf[i][0] + bc[0], accf[i][1] + bc[1],
                                   accf[i][2] + bc[2], accf[i][3] + bc[3]);
            *reinterpret_cast<float4*>(out + (size_t)row * OUTC + tx * 4) = o;
        }
    }
}

extern "C" void kernel_launch(void* const* d_in, const int* in_sizes, int n_in,
                              void* d_out, int out_size) {
    const float* x   = (const float*)d_in[0];
    const int*   e1r = (const int*)d_in[1];
    const int*   e1c = (const int*)d_in[2];
    const float* e1v = (const float*)d_in[3];
    const int*   e2r = (const int*)d_in[4];
    const int*   e2c = (const int*)d_in[5];
    const float* e2v = (const float*)d_in[6];
    const float* We  = (const float*)d_in[7];
    const float* be  = (const float*)d_in[8];
    const float* g0  = (const float*)d_in[9];
    const float* b0  = (const float*)d_in[10];
    const float* g1  = (const float*)d_in[11];
    const float* b1  = (const float*)d_in[12];
    const float* Wh  = (const float*)d_in[13];
    const float* bh  = (const float*)d_in[14];
    float* out = (float*)d_out;

    const int E1 = in_sizes[1];
    const int E2 = in_sizes[4];

    static cudaStream_t s2 = nullptr;
    static cudaEvent_t evA = nullptr, evB = nullptr, evC = nullptr, evD = nullptr;
    if (!s2) {
        cudaStreamCreateWithFlags(&s2, cudaStreamNonBlocking);
        cudaEventCreateWithFlags(&evA, cudaEventDisableTiming);
        cudaEventCreateWithFlags(&evB, cudaEventDisableTiming);
        cudaEventCreateWithFlags(&evC, cudaEventDisableTiming);
        cudaEventCreateWithFlags(&evD, cudaEventDisableTiming);
    }

    // fork: binning on s2, embed on default stream
    cudaEventRecord(evA, 0);
    cudaStreamWaitEvent(s2, evA, 0);

    zero_small_kernel<<<(NN + 255) / 256, 256, 0, s2>>>();
    hist_kernel<<<(E1 + 255) / 256, 256, 0, s2>>>(e1r, E1, 0);
    hist_kernel<<<(E2 + 255) / 256, 256, 0, s2>>>(e2r, E2, 1);
    scan_partial_kernel<<<2 * NBLK, 256, 0, s2>>>();
    scan_tops_kernel<<<1, 512, 0, s2>>>();
    scan_add_kernel<<<2 * NBLK, 256, 0, s2>>>();
    scatter_kernel<<<(E1 + 255) / 256, 256, 0, s2>>>(e1r, e1c, e1v, E1, 0);
    scatter_kernel<<<(E2 + 255) / 256, 256, 0, s2>>>(e2r, e2c, e2v, E2, 1);

    embed_kernel<<<NN / 16, dim3(64, 4)>>>(x, We, be);

    cudaEventRecord(evB, s2);
    cudaStreamWaitEvent(0, evB, 0);

    const int gblocks = (NN + 7) / 8;  // 8 warps (rows) per 256-thread block

    // conv1: h16 -> c0 raw (fp32 J + fp16 mirror), cols [64,192)
    conv_kernel<2, 0, 1><<<gblocks, 256>>>(0, 64);

    // bn0 stats + fused finalize
    bn_stats_kernel<<<(NN + 127) / 128, 128>>>(64, 128, 0, 128, 0, g0, b0);

    // conv2: bn0(c0_16) -> c1 raw (fp32 J + fp16 mirror), cols [192,448)
    conv_kernel<4, 1, 1><<<gblocks, 256>>>(64, 192);

    // bn1 stats + fused finalize
    bn_stats_kernel<<<(NN + 127) / 128, 256>>>(192, 256, 256, 128, 1, g1, b1);

    // prescale overlapped with conv3 on s2 (depends only on BN scales)
    cudaEventRecord(evC, 0);
    cudaStreamWaitEvent(s2, evC, 0);
    head_prescale_kernel<<<1, 1024, 0, s2>>>(Wh, bh);
    cudaEventRecord(evD, s2);

    // conv3: bn1(c1_16) -> c2 (fp32 only), cols [448,960)
    conv_kernel<8, 2, 0><<<gblocks, 256>>>(192, 448);

    // head GEMM after prescale + conv3
    cudaStreamWaitEvent(0, evD, 0);
    head_kernel<<<(NN + 127) / 128, 256>>>(out);
}

// round 16
// speedup vs baseline: 1.1171x; 1.0038x over previous
#include <cuda_runtime.h>
#include <cuda_fp16.h>
#include <cstdint>

#define NN 50000
#define DIM_IN 256
#define HID 64
#define JC 960          // 15*HID concat width
#define MC 448          // mirror width: h(64)+c0raw(128)+c1raw(256)
#define OUTC 32
#define BN_EPS 1e-5f
#define E1MAX 800000
#define E2MAX 1600000
#define NBLK 196        // ceil(NN/256)

#define PACK_F32X2(out, lo, hi) \
    asm("mov.b64 %0, {%1, %2};" : "=l"(out) : "f"(lo), "f"(hi))
#define UNPACK_F32X2(lo, hi, in) \
    asm("mov.b64 {%0, %1}, %2;" : "=f"(lo), "=f"(hi) : "l"(in))
#define FMA_F32X2(d, a, b, c) \
    asm("fma.rn.f32x2 %0, %1, %2, %3;" : "=l"(d) : "l"(a), "l"(b), "l"(c))

// Persistent scratch: J = [h(64) | c0raw(128) | c1raw(256) | c2(512)] per row (fp32, exact).
__device__ float  d_J[(size_t)NN * JC];          // 192 MB
// fp16 mirror of gather sources only: [h | c0raw | c1raw]
__device__ __half d_M[(size_t)NN * MC];          // 44.8 MB
__device__ double d_stats[768];
__device__ unsigned d_bnctr[2];
__device__ float d_scale0[128], d_shift0[128];
__device__ float d_scale1[256], d_shift1[256];
__device__ float d_Wh2[JC * OUTC];
__device__ float d_bh2[OUTC];
__device__ float d_hpart[(size_t)NN * OUTC];     // head partial (cols 0..448 contribution)

// CSR-by-destination bins
__device__ int   d_deg1[NN], d_deg2[NN];
__device__ int   d_pos1[NN], d_pos2[NN];
__device__ int   d_ptr1[NN + 1], d_ptr2[NN + 1];
__device__ int   d_tmp1[NN], d_tmp2[NN];
__device__ int   d_bsum[2][256], d_boff[2][256];
__device__ __align__(16) int2 d_e1[E1MAX];
__device__ __align__(16) int2 d_e2[E2MAX];

// ---------------- zero / binning ----------------
__global__ void zero_small_kernel() {
    int i = blockIdx.x * blockDim.x + threadIdx.x;
    if (i < 768) d_stats[i] = 0.0;
    if (i < 2) d_bnctr[i] = 0u;
    if (i < NN) { d_deg1[i] = 0; d_deg2[i] = 0; d_pos1[i] = 0; d_pos2[i] = 0; }
}

__global__ void hist_kernel(const int* __restrict__ rows, int nE, int which) {
    int i = blockIdx.x * blockDim.x + threadIdx.x;
    if (i >= nE) return;
    int r = rows[i];
    atomicAdd(which ? &d_deg2[r] : &d_deg1[r], 1);
}

__global__ void scan_partial_kernel() {
    int g = blockIdx.x / NBLK;
    int blk = blockIdx.x - g * NBLK;
    const int* deg = g ? d_deg2 : d_deg1;
    int* tmp = g ? d_tmp2 : d_tmp1;

    int tid = threadIdx.x;
    int lane = tid & 31, w = tid >> 5;
    int i = blk * 256 + tid;
    int orig = (i < NN) ? deg[i] : 0;
    int v = orig;
#pragma unroll
    for (int o = 1; o < 32; o <<= 1) {
        int t = __shfl_up_sync(0xffffffffu, v, o);
        if (lane >= o) v += t;
    }
    __shared__ int wsum[8];
    if (lane == 31) wsum[w] = v;
    __syncthreads();
    if (w == 0) {
        int s = (lane < 8) ? wsum[lane] : 0;
#pragma unroll
        for (int o = 1; o < 8; o <<= 1) {
            int t = __shfl_up_sync(0xffffffffu, s, o);
            if (lane >= o) s += t;
        }
        if (lane < 8) wsum[lane] = s;
    }
    __syncthreads();
    int incl = v + (w > 0 ? wsum[w - 1] : 0);
    if (i < NN) tmp[i] = incl;
    if (tid == 255) d_bsum[g][blk] = incl;
}

__global__ void scan_tops_kernel() {
    __shared__ int sh[2][256];
    int g = threadIdx.x >> 8;
    int t = threadIdx.x & 255;
    int orig = (t < NBLK) ? d_bsum[g][t] : 0;
    sh[g][t] = orig;
    __syncthreads();
    for (int off = 1; off < 256; off <<= 1) {
        int add = (t >= off) ? sh[g][t - off] : 0;
        __syncthreads();
        sh[g][t] += add;
        __syncthreads();
    }
    d_boff[g][t] = sh[g][t] - orig;
}

__global__ void scan_add_kernel() {
    int g = blockIdx.x / NBLK;
    int blk = blockIdx.x - g * NBLK;
    int i = blk * 256 + threadIdx.x;
    if (i >= NN) return;
    const int* deg = g ? d_deg2 : d_deg1;
    const int* tmp = g ? d_tmp2 : d_tmp1;
    int* ptr = g ? d_ptr2 : d_ptr1;
    int off = d_boff[g][blk];
    int incl = tmp[i] + off;
    ptr[i] = incl - deg[i];
    if (i == NN - 1) ptr[NN] = incl;
}

__global__ void scatter_kernel(const int* __restrict__ rows,
                               const int* __restrict__ cols,
                               const float* __restrict__ vals,
                               int nE, int which) {
    int i = blockIdx.x * blockDim.x + threadIdx.x;
    if (i >= nE) return;
    int r = rows[i];
    int2 e = make_int2(cols[i], __float_as_int(vals[i]));
    if (which) {
        int p = d_ptr2[r] + atomicAdd(&d_pos2[r], 1);
        d_e2[p] = e;
    } else {
        int p = d_ptr1[r] + atomicAdd(&d_pos1[r], 1);
        d_e1[p] = e;
    }
}

// ---------------- embed: J[:,0:64] = relu(x @ W + b); mirror to d_M ----------------
__global__ void embed_kernel(const float* __restrict__ x,
                             const float* __restrict__ W,
                             const float* __restrict__ b) {
    __shared__ float Ws[64][64];
    __shared__ float xs[16][64];
    const int tx = threadIdx.x;
    const int ty = threadIdx.y;
    const int tid = ty * 64 + tx;
    const int row0 = blockIdx.x * 16;

    float acc[4] = {0.f, 0.f, 0.f, 0.f};
    for (int kt = 0; kt < 4; kt++) {
        for (int i = tid; i < 64 * 64; i += 256)
            Ws[i >> 6][i & 63] = W[(kt * 64 + (i >> 6)) * HID + (i & 63)];
        for (int i = tid; i < 16 * 64; i += 256)
            xs[i >> 6][i & 63] = x[(size_t)(row0 + (i >> 6)) * DIM_IN + kt * 64 + (i & 63)];
        __syncthreads();
#pragma unroll 16
        for (int kk = 0; kk < 64; kk++) {
            float wv = Ws[kk][tx];
#pragma unroll
            for (int r = 0; r < 4; r++) acc[r] += xs[ty * 4 + r][kk] * wv;
        }
        __syncthreads();
    }
    float bb = b[tx];
#pragma unroll
    for (int r = 0; r < 4; r++) {
        float v = acc[r] + bb;
        v = v > 0.f ? v : 0.f;
        int row = row0 + ty * 4 + r;
        d_J[(size_t)row * JC + tx] = v;
        d_M[(size_t)row * MC + tx] = __float2half_rn(v);
    }
}

// ---------------- fused SpMM gather from fp16 mirror (+ BN fold) ----------------
template <int C>
__device__ __forceinline__ void accum_row16(float* acc, const __half* __restrict__ src,
                                            int lane, float v) {
    if constexpr (C == 2) {
        __half2 h = *reinterpret_cast<const __half2*>(src + lane * 2);
        float2 f = __half22float2(h);
        acc[0] += v * f.x; acc[1] += v * f.y;
    } else if constexpr (C == 4) {
        uint2 u = *reinterpret_cast<const uint2*>(src + lane * 4);
        float2 f0 = __half22float2(*reinterpret_cast<const __half2*>(&u.x));
        float2 f1 = __half22float2(*reinterpret_cast<const __half2*>(&u.y));
        acc[0] += v * f0.x; acc[1] += v * f0.y; acc[2] += v * f1.x; acc[3] += v * f1.y;
    } else {
        uint2 a = *reinterpret_cast<const uint2*>(src + lane * 4);
        uint2 bq = *reinterpret_cast<const uint2*>(src + 128 + lane * 4);
        float2 f0 = __half22float2(*reinterpret_cast<const __half2*>(&a.x));
        float2 f1 = __half22float2(*reinterpret_cast<const __half2*>(&a.y));
        float2 f2 = __half22float2(*reinterpret_cast<const __half2*>(&bq.x));
        float2 f3 = __half22float2(*reinterpret_cast<const __half2*>(&bq.y));
        acc[0] += v * f0.x; acc[1] += v * f0.y; acc[2] += v * f1.x; acc[3] += v * f1.y;
        acc[4] += v * f2.x; acc[5] += v * f2.y; acc[6] += v * f3.x; acc[7] += v * f3.y;
    }
}

template <int C, int NEED_SUM>
__device__ __forceinline__ float gather_one(const int2* __restrict__ edges,
                                            int s, int e, const __half* __restrict__ base,
                                            int lane, float* acc) {
#pragma unroll
    for (int i = 0; i < C; i++) acc[i] = 0.f;
    float sumv = 0.f;
    int j = s;
    if ((j & 1) && j < e) {
        int2 cv = __ldg(edges + j);
        float v = __int_as_float(cv.y);
        if constexpr (NEED_SUM) sumv += v;
        accum_row16<C>(acc, base + (size_t)cv.x * MC, lane, v);
        j++;
    }
    for (; j + 8 <= e; j += 8) {
        int4 q[4];
        const int4* p = reinterpret_cast<const int4*>(edges + j);
#pragma unroll
        for (int u = 0; u < 4; u++) q[u] = __ldg(p + u);
#pragma unroll
        for (int u = 0; u < 4; u++) {
            float v0 = __int_as_float(q[u].y);
            float v1 = __int_as_float(q[u].w);
            if constexpr (NEED_SUM) sumv += v0;
            accum_row16<C>(acc, base + (size_t)q[u].x * MC, lane, v0);
            if constexpr (NEED_SUM) sumv += v1;
            accum_row16<C>(acc, base + (size_t)q[u].z * MC, lane, v1);
        }
    }
    for (; j < e; j++) {
        int2 cv = __ldg(edges + j);
        float v = __int_as_float(cv.y);
        if constexpr (NEED_SUM) sumv += v;
        accum_row16<C>(acc, base + (size_t)cv.x * MC, lane, v);
    }
    return sumv;
}

// FOLD: 0 none, 1 bn0, 2 bn1 (applied to gathered input). MIRROR: write fp16 copy.
template <int C, int FOLD, int MIRROR>
__device__ __forceinline__ void store_acc(float* dst, __half* mdst, int lane,
                                          const float* acc, float sumv) {
    const float* sc = (FOLD == 1) ? d_scale0 : d_scale1;
    const float* sh = (FOLD == 1) ? d_shift0 : d_shift1;
    if constexpr (C == 2) {
        float2 o;
        if constexpr (FOLD) {
            o.x = acc[0] * sc[lane * 2] + sumv * sh[lane * 2];
            o.y = acc[1] * sc[lane * 2 + 1] + sumv * sh[lane * 2 + 1];
        } else { o.x = acc[0]; o.y = acc[1]; }
        *reinterpret_cast<float2*>(dst + lane * 2) = o;
        if constexpr (MIRROR)
            *reinterpret_cast<__half2*>(mdst + lane * 2) = __floats2half2_rn(o.x, o.y);
    } else if constexpr (C == 4) {
        float4 o;
        if constexpr (FOLD) {
            o.x = acc[0] * sc[lane * 4] + sumv * sh[lane * 4];
            o.y = acc[1] * sc[lane * 4 + 1] + sumv * sh[lane * 4 + 1];
            o.z = acc[2] * sc[lane * 4 + 2] + sumv * sh[lane * 4 + 2];
            o.w = acc[3] * sc[lane * 4 + 3] + sumv * sh[lane * 4 + 3];
        } else { o.x = acc[0]; o.y = acc[1]; o.z = acc[2]; o.w = acc[3]; }
        *reinterpret_cast<float4*>(dst + lane * 4) = o;
        if constexpr (MIRROR) {
            __half2 h0 = __floats2half2_rn(o.x, o.y);
            __half2 h1 = __floats2half2_rn(o.z, o.w);
            uint2 u = make_uint2(*reinterpret_cast<uint32_t*>(&h0),
                                 *reinterpret_cast<uint32_t*>(&h1));
            *reinterpret_cast<uint2*>(mdst + lane * 4) = u;
        }
    } else {
        float4 oa, ob;
        if constexpr (FOLD) {
            oa.x = acc[0] * sc[lane * 4] + sumv * sh[lane * 4];
            oa.y = acc[1] * sc[lane * 4 + 1] + sumv * sh[lane * 4 + 1];
            oa.z = acc[2] * sc[lane * 4 + 2] + sumv * sh[lane * 4 + 2];
            oa.w = acc[3] * sc[lane * 4 + 3] + sumv * sh[lane * 4 + 3];
            ob.x = acc[4] * sc[128 + lane * 4] + sumv * sh[128 + lane * 4];
            ob.y = acc[5] * sc[128 + lane * 4 + 1] + sumv * sh[128 + lane * 4 + 1];
            ob.z = acc[6] * sc[128 + lane * 4 + 2] + sumv * sh[128 + lane * 4 + 2];
            ob.w = acc[7] * sc[128 + lane * 4 + 3] + sumv * sh[128 + lane * 4 + 3];
        } else {
            oa.x = acc[0]; oa.y = acc[1]; oa.z = acc[2]; oa.w = acc[3];
            ob.x = acc[4]; ob.y = acc[5]; ob.z = acc[6]; ob.w = acc[7];
        }
        *reinterpret_cast<float4*>(dst + lane * 4) = oa;
        *reinterpret_cast<float4*>(dst + 128 + lane * 4) = ob;
    }
}

template <int C, int FOLD, int MIRROR>
__global__ void conv_kernel(int in_off, int out_off) {
    int row = (blockIdx.x * blockDim.x + threadIdx.x) >> 5;
    if (row >= NN) return;
    int lane = threadIdx.x & 31;
    const __half* base = d_M + in_off;
    float* dst = d_J + (size_t)row * JC + out_off;
    __half* mdst = d_M + (size_t)row * MC + out_off;
    float acc[C];

    constexpr int NS = (FOLD != 0);
    float sv = gather_one<C, NS>(d_e1, __ldg(d_ptr1 + row), __ldg(d_ptr1 + row + 1), base, lane, acc);
    store_acc<C, FOLD, MIRROR>(dst, mdst, lane, acc, sv);

    sv = gather_one<C, NS>(d_e2, __ldg(d_ptr2 + row), __ldg(d_ptr2 + row + 1), base, lane, acc);
    store_acc<C, FOLD, MIRROR>(dst + 32 * C, mdst + 32 * C, lane, acc, sv);
}

// ---------------- BatchNorm stats + fused finalize (last-block pattern) ----------------
__global__ void bn_stats_kernel(int off, int D, int statOff, int rowsPerBlock, int which,
                                const float* __restrict__ gamma,
                                const float* __restrict__ beta) {
    int f = threadIdx.x;
    int r0 = blockIdx.x * rowsPerBlock;
    int r1 = r0 + rowsPerBlock;
    if (r1 > NN) r1 = NN;
    float s = 0.f, q = 0.f;
    for (int r = r0; r < r1; r++) {
        float v = d_J[(size_t)r * JC + off + f];
        s += v;
        q += v * v;
    }
    atomicAdd(&d_stats[statOff + f], (double)s);
    atomicAdd(&d_stats[statOff + D + f], (double)q);

    __threadfence();
    __syncthreads();
    __shared__ bool isLast;
    if (f == 0) {
        unsigned t = atomicAdd(&d_bnctr[which], 1u);
        isLast = (t == gridDim.x - 1);
    }
    __syncthreads();
    if (isLast) {
        double sum, sq;
        asm volatile("ld.global.cg.f64 %0, [%1];" : "=d"(sum) : "l"(d_stats + statOff + f));
        asm volatile("ld.global.cg.f64 %0, [%1];" : "=d"(sq)  : "l"(d_stats + statOff + D + f));
        double m = sum / (double)NN;
        double var = sq / (double)NN - m * m;
        float sc = gamma[f] * rsqrtf((float)var + BN_EPS);
        float sh = beta[f] - (float)m * sc;
        if (which) { d_scale1[f] = sc; d_shift1[f] = sh; }
        else       { d_scale0[f] = sc; d_shift0[f] = sh; }
    }
}

// ---------------- head prescale: W' = sc*W, b' = b + sum sh*W ----------------
__global__ void head_prescale_kernel(const float* __restrict__ W,
                                     const float* __restrict__ b) {
    __shared__ float red[32][33];
    int t = threadIdx.x;
    int c = t & 31;
    int fg = t >> 5;   // 0..31
    float partial = 0.f;
    for (int f = fg; f < JC; f += 32) {
        float w = W[f * OUTC + c];
        float sc = 1.f, sh = 0.f;
        if (f >= 64 && f < 192) { sc = d_scale0[f - 64]; sh = d_shift0[f - 64]; }
        else if (f >= 192 && f < 448) { sc = d_scale1[f - 192]; sh = d_shift1[f - 192]; }
        d_Wh2[f * OUTC + c] = w * sc;
        partial += sh * w;
    }
    red[fg][c] = partial;
    __syncthreads();
    if (fg == 0) {
        float s = 0.f;
#pragma unroll
        for (int k = 0; k < 32; k++) s += red[k][c];
        d_bh2[c] = b[c] + s;
    }
}

// ---------------- head: out = J @ W' + b', split at col 448 ----------------
// KT=32. MODE 0: tiles [T0,T1) -> write partial. MODE 1: tiles [T0,T1) + partial + bias -> out.
#define HKT 32
template <int T0, int T1, int MODE>
__global__ void head_kernel(float* __restrict__ out) {
    __shared__ float xs[HKT][132];  // [kk][row], padded stride
    __shared__ float Ws[HKT][32];
    const int tid = threadIdx.x;    // 256
    const int tx = tid & 7;         // col group: cols tx*4..tx*4+3
    const int ty = tid >> 3;        // row group: rows ty*4..ty*4+3 (0..31)
    const int row0 = blockIdx.x * 128;

    unsigned long long acc2[2][4];
#pragma unroll
    for (int p = 0; p < 2; p++)
#pragma unroll
        for (int j = 0; j < 4; j++) acc2[p][j] = 0ull;

    for (int kt = T0; kt < T1; kt++) {
#pragma unroll
        for (int k = 0; k < 4; k++) {
            int idx4 = tid + k * 256;            // 0..1023
            int kk4 = idx4 & 7;                  // HKT/4 = 8
            int r = idx4 >> 3;
            float4 v = make_float4(0.f, 0.f, 0.f, 0.f);
            int row = row0 + r;
            if (row < NN)
                v = *reinterpret_cast<const float4*>(d_J + (size_t)row * JC + kt * HKT + kk4 * 4);
            xs[kk4 * 4 + 0][r] = v.x;
            xs[kk4 * 4 + 1][r] = v.y;
            xs[kk4 * 4 + 2][r] = v.z;
            xs[kk4 * 4 + 3][r] = v.w;
        }
#pragma unroll
        for (int k = 0; k < 4; k++) {
            int idx = tid + k * 256;             // 0..1023
            int fl = idx >> 5;
            int c = idx & 31;
            Ws[fl][c] = d_Wh2[(kt * HKT + fl) * OUTC + c];
        }
        __syncthreads();
#pragma unroll 8
        for (int kk = 0; kk < HKT; kk++) {
            unsigned long long xp0 = *reinterpret_cast<const unsigned long long*>(&xs[kk][ty * 4]);
            unsigned long long xp1 = *reinterpret_cast<const unsigned long long*>(&xs[kk][ty * 4 + 2]);
            float4 wv = *reinterpret_cast<const float4*>(&Ws[kk][tx * 4]);
            unsigned long long w0, w1, w2, w3;
            PACK_F32X2(w0, wv.x, wv.x);
            PACK_F32X2(w1, wv.y, wv.y);
            PACK_F32X2(w2, wv.z, wv.z);
            PACK_F32X2(w3, wv.w, wv.w);
            FMA_F32X2(acc2[0][0], xp0, w0, acc2[0][0]);
            FMA_F32X2(acc2[0][1], xp0, w1, acc2[0][1]);
            FMA_F32X2(acc2[0][2], xp0, w2, acc2[0][2]);
            FMA_F32X2(acc2[0][3], xp0, w3, acc2[0][3]);
            FMA_F32X2(acc2[1][0], xp1, w0, acc2[1][0]);
            FMA_F32X2(acc2[1][1], xp1, w1, acc2[1][1]);
            FMA_F32X2(acc2[1][2], xp1, w2, acc2[1][2]);
            FMA_F32X2(acc2[1][3], xp1, w3, acc2[1][3]);
        }
        __syncthreads();
    }

    float accf[4][4];
#pragma unroll
    for (int p = 0; p < 2; p++)
#pragma unroll
        for (int j = 0; j < 4; j++) {
            float lo, hi;
            UNPACK_F32X2(lo, hi, acc2[p][j]);
            accf[2 * p][j] = lo;
            accf[2 * p + 1][j] = hi;
        }

    if constexpr (MODE == 0) {
#pragma unroll
        for (int i = 0; i < 4; i++) {
            int row = row0 + ty * 4 + i;
            if (row < NN) {
                float4 o = make_float4(accf[i][0], accf[i][1], accf[i][2], accf[i][3]);
                *reinterpret_cast<float4*>(d_hpart + (size_t)row * OUTC + tx * 4) = o;
            }
        }
    } else {
        float4 bb = *reinterpret_cast<const float4*>(d_bh2 + tx * 4);
#pragma unroll
        for (int i = 0; i < 4; i++) {
            int row = row0 + ty * 4 + i;
            if (row < NN) {
                float4 pp = *reinterpret_cast<const float4*>(d_hpart + (size_t)row * OUTC + tx * 4);
                float4 o = make_float4(pp.x + accf[i][0] + bb.x, pp.y + accf[i][1] + bb.y,
                                       pp.z + accf[i][2] + bb.z, pp.w + accf[i][3] + bb.w);
                *reinterpret_cast<float4*>(out + (size_t)row * OUTC + tx * 4) = o;
            }
        }
    }
}

extern "C" void kernel_launch(void* const* d_in, const int* in_sizes, int n_in,
                              void* d_out, int out_size) {
    const float* x   = (const float*)d_in[0];
    const int*   e1r = (const int*)d_in[1];
    const int*   e1c = (const int*)d_in[2];
    const float* e1v = (const float*)d_in[3];
    const int*   e2r = (const int*)d_in[4];
    const int*   e2c = (const int*)d_in[5];
    const float* e2v = (const float*)d_in[6];
    const float* We  = (const float*)d_in[7];
    const float* be  = (const float*)d_in[8];
    const float* g0  = (const float*)d_in[9];
    const float* b0  = (const float*)d_in[10];
    const float* g1  = (const float*)d_in[11];
    const float* b1  = (const float*)d_in[12];
    const float* Wh  = (const float*)d_in[13];
    const float* bh  = (const float*)d_in[14];
    float* out = (float*)d_out;

    const int E1 = in_sizes[1];
    const int E2 = in_sizes[4];

    static cudaStream_t s2 = nullptr;
    static cudaEvent_t evA = nullptr, evB = nullptr, evC = nullptr, evD = nullptr;
    if (!s2) {
        cudaStreamCreateWithFlags(&s2, cudaStreamNonBlocking);
        cudaEventCreateWithFlags(&evA, cudaEventDisableTiming);
        cudaEventCreateWithFlags(&evB, cudaEventDisableTiming);
        cudaEventCreateWithFlags(&evC, cudaEventDisableTiming);
        cudaEventCreateWithFlags(&evD, cudaEventDisableTiming);
    }

    // fork: binning on s2, embed on default stream
    cudaEventRecord(evA, 0);
    cudaStreamWaitEvent(s2, evA, 0);

    zero_small_kernel<<<(NN + 255) / 256, 256, 0, s2>>>();
    hist_kernel<<<(E1 + 255) / 256, 256, 0, s2>>>(e1r, E1, 0);
    hist_kernel<<<(E2 + 255) / 256, 256, 0, s2>>>(e2r, E2, 1);
    scan_partial_kernel<<<2 * NBLK, 256, 0, s2>>>();
    scan_tops_kernel<<<1, 512, 0, s2>>>();
    scan_add_kernel<<<2 * NBLK, 256, 0, s2>>>();
    scatter_kernel<<<(E1 + 255) / 256, 256, 0, s2>>>(e1r, e1c, e1v, E1, 0);
    scatter_kernel<<<(E2 + 255) / 256, 256, 0, s2>>>(e2r, e2c, e2v, E2, 1);

    embed_kernel<<<NN / 16, dim3(64, 4)>>>(x, We, be);

    cudaEventRecord(evB, s2);
    cudaStreamWaitEvent(0, evB, 0);

    const int gblocks = (NN + 7) / 8;
    const int hblocks = (NN + 127) / 128;

    // conv1: h16 -> c0 raw (fp32 J + fp16 mirror), cols [64,192)
    conv_kernel<2, 0, 1><<<gblocks, 256>>>(0, 64);

    // bn0 stats + fused finalize
    bn_stats_kernel<<<(NN + 127) / 128, 128>>>(64, 128, 0, 128, 0, g0, b0);

    // conv2: bn0(c0_16) -> c1 raw (fp32 J + fp16 mirror), cols [192,448)
    conv_kernel<4, 1, 1><<<gblocks, 256>>>(64, 192);

    // bn1 stats + fused finalize
    bn_stats_kernel<<<(NN + 127) / 128, 256>>>(192, 256, 256, 128, 1, g1, b1);

    // s2: prescale, then head part 1 (J cols 0..448 -> partial), overlapping conv3.
    // No hazard: part 1 reads J cols [0,448); conv3 writes cols [448,960).
    cudaEventRecord(evC, 0);
    cudaStreamWaitEvent(s2, evC, 0);
    head_prescale_kernel<<<1, 1024, 0, s2>>>(Wh, bh);
    head_kernel<0, 14, 0><<<hblocks, 256, 0, s2>>>(out);   // tiles 0..13 = cols 0..448
    cudaEventRecord(evD, s2);

    // conv3: bn1(c1_16) -> c2 (fp32 only), cols [448,960)
    conv_kernel<8, 2, 0><<<gblocks, 256>>>(192, 448);

    // head part 2: tiles 14..29 = cols 448..960, + partial + bias -> out
    cudaStreamWaitEvent(0, evD, 0);
    head_kernel<14, 30, 1><<<hblocks, 256>>>(out);
}

// round 17
// speedup vs baseline: 1.1191x; 1.0018x over previous
#include <cuda_runtime.h>
#include <cuda_fp16.h>
#include <cstdint>

#define NN 50000
#define DIM_IN 256
#define HID 64
#define JC 960          // 15*HID concat width
#define MC 448          // mirror width: h(64)+c0raw(128)+c1raw(256)
#define OUTC 32
#define BN_EPS 1e-5f
#define E1MAX 800000
#define E2MAX 1600000
#define NBLK 196        // ceil(NN/256)

#define PACK_F32X2(out, lo, hi) \
    asm("mov.b64 %0, {%1, %2};" : "=l"(out) : "f"(lo), "f"(hi))
#define UNPACK_F32X2(lo, hi, in) \
    asm("mov.b64 {%0, %1}, %2;" : "=f"(lo), "=f"(hi) : "l"(in))
#define FMA_F32X2(d, a, b, c) \
    asm("fma.rn.f32x2 %0, %1, %2, %3;" : "=l"(d) : "l"(a), "l"(b), "l"(c))

// Persistent scratch: J = [h(64) | c0raw(128) | c1raw(256) | c2(512)] per row (fp32, exact).
__device__ float  d_J[(size_t)NN * JC];          // 192 MB
// fp16 mirror of gather sources only: [h | c0raw | c1raw]
__device__ __half d_M[(size_t)NN * MC];          // 44.8 MB
__device__ double d_stats[768];
__device__ unsigned d_bnctr[2];
__device__ float d_scale0[128], d_shift0[128];
__device__ float d_scale1[256], d_shift1[256];
__device__ float d_Wh2[JC * OUTC];
__device__ float d_bh2[OUTC];
__device__ float d_hpart[(size_t)NN * OUTC];     // head partial (cols 0..448 contribution)

// CSR-by-destination bins
__device__ int   d_deg1[NN], d_deg2[NN];
__device__ int   d_pos1[NN], d_pos2[NN];
__device__ int   d_ptr1[NN + 1], d_ptr2[NN + 1];
__device__ int   d_tmp1[NN], d_tmp2[NN];
__device__ int   d_bsum[2][256], d_boff[2][256];
__device__ __align__(16) int2 d_e1[E1MAX];
__device__ __align__(16) int2 d_e2[E2MAX];

// ---------------- zero / binning ----------------
__global__ void zero_small_kernel() {
    int i = blockIdx.x * blockDim.x + threadIdx.x;
    if (i < 768) d_stats[i] = 0.0;
    if (i < 2) d_bnctr[i] = 0u;
    if (i < NN) { d_deg1[i] = 0; d_deg2[i] = 0; d_pos1[i] = 0; d_pos2[i] = 0; }
}

// single launch covers both graphs: [0,E1) -> graph1, [E1,E1+E2) -> graph2
__global__ void hist_kernel(const int* __restrict__ r1, const int* __restrict__ r2,
                            int E1, int total) {
    int i = blockIdx.x * blockDim.x + threadIdx.x;
    if (i >= total) return;
    if (i < E1) atomicAdd(&d_deg1[r1[i]], 1);
    else        atomicAdd(&d_deg2[r2[i - E1]], 1);
}

__global__ void scan_partial_kernel() {
    int g = blockIdx.x / NBLK;
    int blk = blockIdx.x - g * NBLK;
    const int* deg = g ? d_deg2 : d_deg1;
    int* tmp = g ? d_tmp2 : d_tmp1;

    int tid = threadIdx.x;
    int lane = tid & 31, w = tid >> 5;
    int i = blk * 256 + tid;
    int orig = (i < NN) ? deg[i] : 0;
    int v = orig;
#pragma unroll
    for (int o = 1; o < 32; o <<= 1) {
        int t = __shfl_up_sync(0xffffffffu, v, o);
        if (lane >= o) v += t;
    }
    __shared__ int wsum[8];
    if (lane == 31) wsum[w] = v;
    __syncthreads();
    if (w == 0) {
        int s = (lane < 8) ? wsum[lane] : 0;
#pragma unroll
        for (int o = 1; o < 8; o <<= 1) {
            int t = __shfl_up_sync(0xffffffffu, s, o);
            if (lane >= o) s += t;
        }
        if (lane < 8) wsum[lane] = s;
    }
    __syncthreads();
    int incl = v + (w > 0 ? wsum[w - 1] : 0);
    if (i < NN) tmp[i] = incl;
    if (tid == 255) d_bsum[g][blk] = incl;
}

__global__ void scan_tops_kernel() {
    __shared__ int sh[2][256];
    int g = threadIdx.x >> 8;
    int t = threadIdx.x & 255;
    int orig = (t < NBLK) ? d_bsum[g][t] : 0;
    sh[g][t] = orig;
    __syncthreads();
    for (int off = 1; off < 256; off <<= 1) {
        int add = (t >= off) ? sh[g][t - off] : 0;
        __syncthreads();
        sh[g][t] += add;
        __syncthreads();
    }
    d_boff[g][t] = sh[g][t] - orig;
}

__global__ void scan_add_kernel() {
    int g = blockIdx.x / NBLK;
    int blk = blockIdx.x - g * NBLK;
    int i = blk * 256 + threadIdx.x;
    if (i >= NN) return;
    const int* deg = g ? d_deg2 : d_deg1;
    const int* tmp = g ? d_tmp2 : d_tmp1;
    int* ptr = g ? d_ptr2 : d_ptr1;
    int off = d_boff[g][blk];
    int incl = tmp[i] + off;
    ptr[i] = incl - deg[i];
    if (i == NN - 1) ptr[NN] = incl;
}

__global__ void scatter_kernel(const int* __restrict__ rows,
                               const int* __restrict__ cols,
                               const float* __restrict__ vals,
                               int nE, int which) {
    int i = blockIdx.x * blockDim.x + threadIdx.x;
    if (i >= nE) return;
    int r = rows[i];
    int2 e = make_int2(cols[i], __float_as_int(vals[i]));
    if (which) {
        int p = d_ptr2[r] + atomicAdd(&d_pos2[r], 1);
        d_e2[p] = e;
    } else {
        int p = d_ptr1[r] + atomicAdd(&d_pos1[r], 1);
        d_e1[p] = e;
    }
}

// ---------------- embed: J[:,0:64] = relu(x @ W + b); mirror to d_M ----------------
__global__ void embed_kernel(const float* __restrict__ x,
                             const float* __restrict__ W,
                             const float* __restrict__ b) {
    __shared__ float Ws[64][64];
    __shared__ float xs[16][64];
    const int tx = threadIdx.x;
    const int ty = threadIdx.y;
    const int tid = ty * 64 + tx;
    const int row0 = blockIdx.x * 16;

    float acc[4] = {0.f, 0.f, 0.f, 0.f};
    for (int kt = 0; kt < 4; kt++) {
        for (int i = tid; i < 64 * 64; i += 256)
            Ws[i >> 6][i & 63] = W[(kt * 64 + (i >> 6)) * HID + (i & 63)];
        for (int i = tid; i < 16 * 64; i += 256)
            xs[i >> 6][i & 63] = x[(size_t)(row0 + (i >> 6)) * DIM_IN + kt * 64 + (i & 63)];
        __syncthreads();
#pragma unroll 16
        for (int kk = 0; kk < 64; kk++) {
            float wv = Ws[kk][tx];
#pragma unroll
            for (int r = 0; r < 4; r++) acc[r] += xs[ty * 4 + r][kk] * wv;
        }
        __syncthreads();
    }
    float bb = b[tx];
#pragma unroll
    for (int r = 0; r < 4; r++) {
        float v = acc[r] + bb;
        v = v > 0.f ? v : 0.f;
        int row = row0 + ty * 4 + r;
        d_J[(size_t)row * JC + tx] = v;
        d_M[(size_t)row * MC + tx] = __float2half_rn(v);
    }
}

// ---------------- fused SpMM gather from fp16 mirror (+ BN fold) ----------------
template <int C>
__device__ __forceinline__ void accum_row16(float* acc, const __half* __restrict__ src,
                                            int lane, float v) {
    if constexpr (C == 2) {
        __half2 h = *reinterpret_cast<const __half2*>(src + lane * 2);
        float2 f = __half22float2(h);
        acc[0] += v * f.x; acc[1] += v * f.y;
    } else if constexpr (C == 4) {
        uint2 u = *reinterpret_cast<const uint2*>(src + lane * 4);
        float2 f0 = __half22float2(*reinterpret_cast<const __half2*>(&u.x));
        float2 f1 = __half22float2(*reinterpret_cast<const __half2*>(&u.y));
        acc[0] += v * f0.x; acc[1] += v * f0.y; acc[2] += v * f1.x; acc[3] += v * f1.y;
    } else {
        uint2 a = *reinterpret_cast<const uint2*>(src + lane * 4);
        uint2 bq = *reinterpret_cast<const uint2*>(src + 128 + lane * 4);
        float2 f0 = __half22float2(*reinterpret_cast<const __half2*>(&a.x));
        float2 f1 = __half22float2(*reinterpret_cast<const __half2*>(&a.y));
        float2 f2 = __half22float2(*reinterpret_cast<const __half2*>(&bq.x));
        float2 f3 = __half22float2(*reinterpret_cast<const __half2*>(&bq.y));
        acc[0] += v * f0.x; acc[1] += v * f0.y; acc[2] += v * f1.x; acc[3] += v * f1.y;
        acc[4] += v * f2.x; acc[5] += v * f2.y; acc[6] += v * f3.x; acc[7] += v * f3.y;
    }
}

// DUAL: use two accumulator banks (even/odd edges) to double independent FMA chains.
template <int C, int NEED_SUM, int DUAL>
__device__ __forceinline__ float gather_one(const int2* __restrict__ edges,
                                            int s, int e, const __half* __restrict__ base,
                                            int lane, float* acc) {
#pragma unroll
    for (int i = 0; i < C; i++) acc[i] = 0.f;
    float accB[DUAL ? C : 1];
#pragma unroll
    for (int i = 0; i < (DUAL ? C : 1); i++) accB[i] = 0.f;

    float sumv = 0.f;
    int j = s;
    if ((j & 1) && j < e) {
        int2 cv = __ldg(edges + j);
        float v = __int_as_float(cv.y);
        if constexpr (NEED_SUM) sumv += v;
        accum_row16<C>(acc, base + (size_t)cv.x * MC, lane, v);
        j++;
    }
    for (; j + 8 <= e; j += 8) {
        int4 q[4];
        const int4* p = reinterpret_cast<const int4*>(edges + j);
#pragma unroll
        for (int u = 0; u < 4; u++) q[u] = __ldg(p + u);
#pragma unroll
        for (int u = 0; u < 4; u++) {
            float v0 = __int_as_float(q[u].y);
            float v1 = __int_as_float(q[u].w);
            if constexpr (NEED_SUM) sumv += v0;
            accum_row16<C>(acc, base + (size_t)q[u].x * MC, lane, v0);
            if constexpr (NEED_SUM) sumv += v1;
            accum_row16<C>(DUAL ? accB : acc, base + (size_t)q[u].z * MC, lane, v1);
        }
    }
    for (; j < e; j++) {
        int2 cv = __ldg(edges + j);
        float v = __int_as_float(cv.y);
        if constexpr (NEED_SUM) sumv += v;
        accum_row16<C>(acc, base + (size_t)cv.x * MC, lane, v);
    }
    if constexpr (DUAL) {
#pragma unroll
        for (int i = 0; i < C; i++) acc[i] += accB[i];
    }
    return sumv;
}

// FOLD: 0 none, 1 bn0, 2 bn1 (applied to gathered input). MIRROR: write fp16 copy.
template <int C, int FOLD, int MIRROR>
__device__ __forceinline__ void store_acc(float* dst, __half* mdst, int lane,
                                          const float* acc, float sumv) {
    const float* sc = (FOLD == 1) ? d_scale0 : d_scale1;
    const float* sh = (FOLD == 1) ? d_shift0 : d_shift1;
    if constexpr (C == 2) {
        float2 o;
        if constexpr (FOLD) {
            o.x = acc[0] * sc[lane * 2] + sumv * sh[lane * 2];
            o.y = acc[1] * sc[lane * 2 + 1] + sumv * sh[lane * 2 + 1];
        } else { o.x = acc[0]; o.y = acc[1]; }
        *reinterpret_cast<float2*>(dst + lane * 2) = o;
        if constexpr (MIRROR)
            *reinterpret_cast<__half2*>(mdst + lane * 2) = __floats2half2_rn(o.x, o.y);
    } else if constexpr (C == 4) {
        float4 o;
        if constexpr (FOLD) {
            o.x = acc[0] * sc[lane * 4] + sumv * sh[lane * 4];
            o.y = acc[1] * sc[lane * 4 + 1] + sumv * sh[lane * 4 + 1];
            o.z = acc[2] * sc[lane * 4 + 2] + sumv * sh[lane * 4 + 2];
            o.w = acc[3] * sc[lane * 4 + 3] + sumv * sh[lane * 4 + 3];
        } else { o.x = acc[0]; o.y = acc[1]; o.z = acc[2]; o.w = acc[3]; }
        *reinterpret_cast<float4*>(dst + lane * 4) = o;
        if constexpr (MIRROR) {
            __half2 h0 = __floats2half2_rn(o.x, o.y);
            __half2 h1 = __floats2half2_rn(o.z, o.w);
            uint2 u = make_uint2(*reinterpret_cast<uint32_t*>(&h0),
                                 *reinterpret_cast<uint32_t*>(&h1));
            *reinterpret_cast<uint2*>(mdst + lane * 4) = u;
        }
    } else {
        float4 oa, ob;
        if constexpr (FOLD) {
            oa.x = acc[0] * sc[lane * 4] + sumv * sh[lane * 4];
            oa.y = acc[1] * sc[lane * 4 + 1] + sumv * sh[lane * 4 + 1];
            oa.z = acc[2] * sc[lane * 4 + 2] + sumv * sh[lane * 4 + 2];
            oa.w = acc[3] * sc[lane * 4 + 3] + sumv * sh[lane * 4 + 3];
            ob.x = acc[4] * sc[128 + lane * 4] + sumv * sh[128 + lane * 4];
            ob.y = acc[5] * sc[128 + lane * 4 + 1] + sumv * sh[128 + lane * 4 + 1];
            ob.z = acc[6] * sc[128 + lane * 4 + 2] + sumv * sh[128 + lane * 4 + 2];
            ob.w = acc[7] * sc[128 + lane * 4 + 3] + sumv * sh[128 + lane * 4 + 3];
        } else {
            oa.x = acc[0]; oa.y = acc[1]; oa.z = acc[2]; oa.w = acc[3];
            ob.x = acc[4]; ob.y = acc[5]; ob.z = acc[6]; ob.w = acc[7];
        }
        *reinterpret_cast<float4*>(dst + lane * 4) = oa;
        *reinterpret_cast<float4*>(dst + 128 + lane * 4) = ob;
    }
}

template <int C, int FOLD, int MIRROR>
__global__ void conv_kernel(int in_off, int out_off) {
    int row = (blockIdx.x * blockDim.x + threadIdx.x) >> 5;
    if (row >= NN) return;
    int lane = threadIdx.x & 31;
    const __half* base = d_M + in_off;
    float* dst = d_J + (size_t)row * JC + out_off;
    __half* mdst = d_M + (size_t)row * MC + out_off;
    float acc[C];

    constexpr int NS = (FOLD != 0);
    constexpr int DU = (C <= 4);   // dual-bank accumulators where chains are scarce
    float sv = gather_one<C, NS, DU>(d_e1, __ldg(d_ptr1 + row), __ldg(d_ptr1 + row + 1), base, lane, acc);
    store_acc<C, FOLD, MIRROR>(dst, mdst, lane, acc, sv);

    sv = gather_one<C, NS, DU>(d_e2, __ldg(d_ptr2 + row), __ldg(d_ptr2 + row + 1), base, lane, acc);
    store_acc<C, FOLD, MIRROR>(dst + 32 * C, mdst + 32 * C, lane, acc, sv);
}

// ---------------- BatchNorm stats + fused finalize (last-block pattern) ----------------
__global__ void bn_stats_kernel(int off, int D, int statOff, int rowsPerBlock, int which,
                                const float* __restrict__ gamma,
                                const float* __restrict__ beta) {
    int f = threadIdx.x;
    int r0 = blockIdx.x * rowsPerBlock;
    int r1 = r0 + rowsPerBlock;
    if (r1 > NN) r1 = NN;
    float s = 0.f, q = 0.f;
    for (int r = r0; r < r1; r++) {
        float v = d_J[(size_t)r * JC + off + f];
        s += v;
        q += v * v;
    }
    atomicAdd(&d_stats[statOff + f], (double)s);
    atomicAdd(&d_stats[statOff + D + f], (double)q);

    __threadfence();
    __syncthreads();
    __shared__ bool isLast;
    if (f == 0) {
        unsigned t = atomicAdd(&d_bnctr[which], 1u);
        isLast = (t == gridDim.x - 1);
    }
    __syncthreads();
    if (isLast) {
        double sum, sq;
        asm volatile("ld.global.cg.f64 %0, [%1];" : "=d"(sum) : "l"(d_stats + statOff + f));
        asm volatile("ld.global.cg.f64 %0, [%1];" : "=d"(sq)  : "l"(d_stats + statOff + D + f));
        double m = sum / (double)NN;
        double var = sq / (double)NN - m * m;
        float sc = gamma[f] * rsqrtf((float)var + BN_EPS);
        float sh = beta[f] - (float)m * sc;
        if (which) { d_scale1[f] = sc; d_shift1[f] = sh; }
        else       { d_scale0[f] = sc; d_shift0[f] = sh; }
    }
}

// ---------------- head prescale: W' = sc*W, b' = b + sum sh*W ----------------
__global__ void head_prescale_kernel(const float* __restrict__ W,
                                     const float* __restrict__ b) {
    __shared__ float red[32][33];
    int t = threadIdx.x;
    int c = t & 31;
    int fg = t >> 5;   // 0..31
    float partial = 0.f;
    for (int f = fg; f < JC; f += 32) {
        float w = W[f * OUTC + c];
        float sc = 1.f, sh = 0.f;
        if (f >= 64 && f < 192) { sc = d_scale0[f - 64]; sh = d_shift0[f - 64]; }
        else if (f >= 192 && f < 448) { sc = d_scale1[f - 192]; sh = d_shift1[f - 192]; }
        d_Wh2[f * OUTC + c] = w * sc;
        partial += sh * w;
    }
    red[fg][c] = partial;
    __syncthreads();
    if (fg == 0) {
        float s = 0.f;
#pragma unroll
        for (int k = 0; k < 32; k++) s += red[k][c];
        d_bh2[c] = b[c] + s;
    }
}

// ---------------- head: out = J @ W' + b', split at col 448 ----------------
#define HKT 32
template <int T0, int T1, int MODE>
__global__ void head_kernel(float* __restrict__ out) {
    __shared__ float xs[HKT][132];
    __shared__ float Ws[HKT][32];
    const int tid = threadIdx.x;    // 256
    const int tx = tid & 7;
    const int ty = tid >> 3;
    const int row0 = blockIdx.x * 128;

    unsigned long long acc2[2][4];
#pragma unroll
    for (int p = 0; p < 2; p++)
#pragma unroll
        for (int j = 0; j < 4; j++) acc2[p][j] = 0ull;

    for (int kt = T0; kt < T1; kt++) {
#pragma unroll
        for (int k = 0; k < 4; k++) {
            int idx4 = tid + k * 256;
            int kk4 = idx4 & 7;
            int r = idx4 >> 3;
            float4 v = make_float4(0.f, 0.f, 0.f, 0.f);
            int row = row0 + r;
            if (row < NN)
                v = *reinterpret_cast<const float4*>(d_J + (size_t)row * JC + kt * HKT + kk4 * 4);
            xs[kk4 * 4 + 0][r] = v.x;
            xs[kk4 * 4 + 1][r] = v.y;
            xs[kk4 * 4 + 2][r] = v.z;
            xs[kk4 * 4 + 3][r] = v.w;
        }
#pragma unroll
        for (int k = 0; k < 4; k++) {
            int idx = tid + k * 256;
            int fl = idx >> 5;
            int c = idx & 31;
            Ws[fl][c] = d_Wh2[(kt * HKT + fl) * OUTC + c];
        }
        __syncthreads();
#pragma unroll 8
        for (int kk = 0; kk < HKT; kk++) {
            unsigned long long xp0 = *reinterpret_cast<const unsigned long long*>(&xs[kk][ty * 4]);
            unsigned long long xp1 = *reinterpret_cast<const unsigned long long*>(&xs[kk][ty * 4 + 2]);
            float4 wv = *reinterpret_cast<const float4*>(&Ws[kk][tx * 4]);
            unsigned long long w0, w1, w2, w3;
            PACK_F32X2(w0, wv.x, wv.x);
            PACK_F32X2(w1, wv.y, wv.y);
            PACK_F32X2(w2, wv.z, wv.z);
            PACK_F32X2(w3, wv.w, wv.w);
            FMA_F32X2(acc2[0][0], xp0, w0, acc2[0][0]);
            FMA_F32X2(acc2[0][1], xp0, w1, acc2[0][1]);
            FMA_F32X2(acc2[0][2], xp0, w2, acc2[0][2]);
            FMA_F32X2(acc2[0][3], xp0, w3, acc2[0][3]);
            FMA_F32X2(acc2[1][0], xp1, w0, acc2[1][0]);
            FMA_F32X2(acc2[1][1], xp1, w1, acc2[1][1]);
            FMA_F32X2(acc2[1][2], xp1, w2, acc2[1][2]);
            FMA_F32X2(acc2[1][3], xp1, w3, acc2[1][3]);
        }
        __syncthreads();
    }

    float accf[4][4];
#pragma unroll
    for (int p = 0; p < 2; p++)
#pragma unroll
        for (int j = 0; j < 4; j++) {
            float lo, hi;
            UNPACK_F32X2(lo, hi, acc2[p][j]);
            accf[2 * p][j] = lo;
            accf[2 * p + 1][j] = hi;
        }

    if constexpr (MODE == 0) {
#pragma unroll
        for (int i = 0; i < 4; i++) {
            int row = row0 + ty * 4 + i;
            if (row < NN) {
                float4 o = make_float4(accf[i][0], accf[i][1], accf[i][2], accf[i][3]);
                *reinterpret_cast<float4*>(d_hpart + (size_t)row * OUTC + tx * 4) = o;
            }
        }
    } else {
        float4 bb = *reinterpret_cast<const float4*>(d_bh2 + tx * 4);
#pragma unroll
        for (int i = 0; i < 4; i++) {
            int row = row0 + ty * 4 + i;
            if (row < NN) {
                float4 pp = *reinterpret_cast<const float4*>(d_hpart + (size_t)row * OUTC + tx * 4);
                float4 o = make_float4(pp.x + accf[i][0] + bb.x, pp.y + accf[i][1] + bb.y,
                                       pp.z + accf[i][2] + bb.z, pp.w + accf[i][3] + bb.w);
                *reinterpret_cast<float4*>(out + (size_t)row * OUTC + tx * 4) = o;
            }
        }
    }
}

extern "C" void kernel_launch(void* const* d_in, const int* in_sizes, int n_in,
                              void* d_out, int out_size) {
    const float* x   = (const float*)d_in[0];
    const int*   e1r = (const int*)d_in[1];
    const int*   e1c = (const int*)d_in[2];
    const float* e1v = (const float*)d_in[3];
    const int*   e2r = (const int*)d_in[4];
    const int*   e2c = (const int*)d_in[5];
    const float* e2v = (const float*)d_in[6];
    const float* We  = (const float*)d_in[7];
    const float* be  = (const float*)d_in[8];
    const float* g0  = (const float*)d_in[9];
    const float* b0  = (const float*)d_in[10];
    const float* g1  = (const float*)d_in[11];
    const float* b1  = (const float*)d_in[12];
    const float* Wh  = (const float*)d_in[13];
    const float* bh  = (const float*)d_in[14];
    float* out = (float*)d_out;

    const int E1 = in_sizes[1];
    const int E2 = in_sizes[4];

    static cudaStream_t s2 = nullptr;
    static cudaEvent_t evA = nullptr, evB = nullptr, evC = nullptr, evD = nullptr;
    if (!s2) {
        cudaStreamCreateWithFlags(&s2, cudaStreamNonBlocking);
        cudaEventCreateWithFlags(&evA, cudaEventDisableTiming);
        cudaEventCreateWithFlags(&evB, cudaEventDisableTiming);
        cudaEventCreateWithFlags(&evC, cudaEventDisableTiming);
        cudaEventCreateWithFlags(&evD, cudaEventDisableTiming);
    }

    // fork: binning on s2, embed on default stream
    cudaEventRecord(evA, 0);
    cudaStreamWaitEvent(s2, evA, 0);

    zero_small_kernel<<<(NN + 255) / 256, 256, 0, s2>>>();
    hist_kernel<<<(E1 + E2 + 255) / 256, 256, 0, s2>>>(e1r, e2r, E1, E1 + E2);
    scan_partial_kernel<<<2 * NBLK, 256, 0, s2>>>();
    scan_tops_kernel<<<1, 512, 0, s2>>>();
    scan_add_kernel<<<2 * NBLK, 256, 0, s2>>>();
    scatter_kernel<<<(E1 + 255) / 256, 256, 0, s2>>>(e1r, e1c, e1v, E1, 0);
    scatter_kernel<<<(E2 + 255) / 256, 256, 0, s2>>>(e2r, e2c, e2v, E2, 1);

    embed_kernel<<<NN / 16, dim3(64, 4)>>>(x, We, be);

    cudaEventRecord(evB, s2);
    cudaStreamWaitEvent(0, evB, 0);

    const int gblocks = (NN + 7) / 8;
    const int hblocks = (NN + 127) / 128;

    // conv1: h16 -> c0 raw (fp32 J + fp16 mirror), cols [64,192)
    conv_kernel<2, 0, 1><<<gblocks, 256>>>(0, 64);

    // bn0 stats + fused finalize
    bn_stats_kernel<<<(NN + 127) / 128, 128>>>(64, 128, 0, 128, 0, g0, b0);

    // conv2: bn0(c0_16) -> c1 raw (fp32 J + fp16 mirror), cols [192,448)
    conv_kernel<4, 1, 1><<<gblocks, 256>>>(64, 192);

    // bn1 stats + fused finalize
    bn_stats_kernel<<<(NN + 127) / 128, 256>>>(192, 256, 256, 128, 1, g1, b1);

    // s2: prescale, then head part 1 (J cols 0..448 -> partial), overlapping conv3.
    cudaEventRecord(evC, 0);
    cudaStreamWaitEvent(s2, evC, 0);
    head_prescale_kernel<<<1, 1024, 0, s2>>>(Wh, bh);
    head_kernel<0, 14, 0><<<hblocks, 256, 0, s2>>>(out);   // tiles 0..13 = cols 0..448
    cudaEventRecord(evD, s2);

    // conv3: bn1(c1_16) -> c2 (fp32 only), cols [448,960)
    conv_kernel<8, 2, 0><<<gblocks, 256>>>(192, 448);

    // head part 2: tiles 14..29 = cols 448..960, + partial + bias -> out
    cudaStreamWaitEvent(0, evD, 0);
    head_kernel<14, 30, 1><<<hblocks, 256>>>(out);
}